// round 11
// baseline (speedup 1.0000x reference)
#include <cuda_runtime.h>
#include <cuda_bf16.h>
#include <cstdint>
#include <math.h>

// ---------------------------------------------------------------------------
// Problem constants
// ---------------------------------------------------------------------------
constexpr int kB  = 4;
constexpr int kC  = 512;
constexpr int kHW = 4096;
constexpr int kG  = 32;
constexpr int kCPG = kC / kG;   // 16
constexpr float kEPS = 1e-6f;

// Scratch (__device__ globals per allocation-free rule)
__device__ __nv_bfloat16 g_hT  [(size_t)kB * kHW * kC];    // GN out [b][n][c]
__device__ __nv_bfloat16 g_qkt [(size_t)kB * kHW * 1024];  // [b][n][q||k]
__device__ __nv_bfloat16 g_v   [(size_t)kB * kC * kHW];    // V [b][c][n]
__device__ __nv_bfloat16 g_o2  [(size_t)kB * kHW * kC];    // attn@V [b][n][c]
__device__ __nv_bfloat16 g_simh[(size_t)kB * kHW * kHW];   // P~ bf16 (128 MB)
__device__ float         g_rs  [(size_t)kB * kHW];         // softmax row sums
__device__ float         g_aff [(size_t)kB * kC * 2];      // (scale, offset)
__device__ __nv_bfloat16 g_wh  [4 * kC * kC];              // bf16 wq,wk,wv,wo
__device__ float         g_bqk [2 * kC];                   // bq || bk

// ---------------------------------------------------------------------------
// Helpers
// ---------------------------------------------------------------------------
__device__ __forceinline__ uint32_t smem_u32(const void* p) {
    uint32_t a;
    asm("{ .reg .u64 t; cvta.to.shared.u64 t, %1; cvt.u32.u64 %0, t; }"
        : "=r"(a) : "l"(p));
    return a;
}
__device__ __forceinline__ void cp16(uint32_t dst, const void* src) {
    asm volatile("cp.async.cg.shared.global [%0], [%1], 16;\n"
                 :: "r"(dst), "l"(src));
}
__device__ __forceinline__ void cp_commit() {
    asm volatile("cp.async.commit_group;\n" ::: "memory");
}
template <int N>
__device__ __forceinline__ void cp_wait() {
    asm volatile("cp.async.wait_group %0;\n" :: "n"(N) : "memory");
}
// m16n8k16 bf16 mma, row.col, fp32 accum
__device__ __forceinline__ void mma16(float* d, const uint32_t* a, const uint32_t* b) {
    asm volatile(
        "mma.sync.aligned.m16n8k16.row.col.f32.bf16.bf16.f32 "
        "{%0,%1,%2,%3}, {%4,%5,%6,%7}, {%8,%9}, {%0,%1,%2,%3};"
        : "+f"(d[0]), "+f"(d[1]), "+f"(d[2]), "+f"(d[3])
        : "r"(a[0]), "r"(a[1]), "r"(a[2]), "r"(a[3]), "r"(b[0]), "r"(b[1]));
}
// ldmatrix 4x (m8n8 b16)
__device__ __forceinline__ void ldsm4(uint32_t* r, uint32_t addr) {
    asm volatile(
        "ldmatrix.sync.aligned.m8n8.x4.shared.b16 {%0,%1,%2,%3}, [%4];"
        : "=r"(r[0]), "=r"(r[1]), "=r"(r[2]), "=r"(r[3]) : "r"(addr));
}

// ---------------------------------------------------------------------------
// Weight prep: bf16 weights + concatenated q/k bias
// ---------------------------------------------------------------------------
__global__ void prep_weights(const float* __restrict__ wq, const float* __restrict__ wk,
                             const float* __restrict__ wv, const float* __restrict__ wo,
                             const float* __restrict__ bq, const float* __restrict__ bk,
                             __nv_bfloat16* __restrict__ wh, float* __restrict__ bqk) {
    const int i = blockIdx.x * blockDim.x + threadIdx.x;
    const int n = kC * kC;
    if (i < n) {
        wh[0 * n + i] = __float2bfloat16_rn(wq[i]);
        wh[1 * n + i] = __float2bfloat16_rn(wk[i]);
        wh[2 * n + i] = __float2bfloat16_rn(wv[i]);
        wh[3 * n + i] = __float2bfloat16_rn(wo[i]);
    }
    if (i < kC)          bqk[i] = bq[i];
    else if (i < 2 * kC) bqk[i] = bk[i - kC];
}

// Zero the softmax row-sum accumulators (graph-replay safe)
__global__ void rs_init(float* __restrict__ rs) {
    rs[blockIdx.x * 256 + threadIdx.x] = 0.f;
}

// ---------------------------------------------------------------------------
// GroupNorm pass 1: per-(b,g) mean/var -> per-channel affine (a, b)
// ---------------------------------------------------------------------------
__global__ void gn_stats(const float* __restrict__ x,
                         const float* __restrict__ gamma,
                         const float* __restrict__ beta,
                         float* __restrict__ aff) {
    const int b = blockIdx.x / kG, g = blockIdx.x % kG;
    const float* xp = x + ((size_t)b * kC + (size_t)g * kCPG) * kHW;
    const int N = kCPG * kHW;

    float s = 0.f, ss = 0.f;
    for (int i = threadIdx.x; i < N; i += 256) {
        float v = xp[i];
        s += v; ss += v * v;
    }
    __shared__ float sh1[256], sh2[256];
    sh1[threadIdx.x] = s; sh2[threadIdx.x] = ss;
    __syncthreads();
    for (int o = 128; o > 0; o >>= 1) {
        if (threadIdx.x < o) {
            sh1[threadIdx.x] += sh1[threadIdx.x + o];
            sh2[threadIdx.x] += sh2[threadIdx.x + o];
        }
        __syncthreads();
    }
    if (threadIdx.x < kCPG) {
        const float mean = sh1[0] / (float)N;
        const float var  = sh2[0] / (float)N - mean * mean;
        const float rinv = rsqrtf(var + kEPS);
        const int ch = g * kCPG + threadIdx.x;
        const float a = rinv * gamma[ch];
        aff[((size_t)b * kC + ch) * 2 + 0] = a;
        aff[((size_t)b * kC + ch) * 2 + 1] = beta[ch] - mean * a;
    }
}

// ---------------------------------------------------------------------------
// GroupNorm pass 2: normalize + transpose + bf16: x[b][c][n] -> hT[b][n][c]
// ---------------------------------------------------------------------------
__global__ void gn_norm_t(const float* __restrict__ x,
                          const float* __restrict__ aff,
                          __nv_bfloat16* __restrict__ hT) {
    __shared__ float t[32][33];
    const int b = blockIdx.z;
    const int n0 = blockIdx.x * 32, c0 = blockIdx.y * 32;
    const int tx = threadIdx.x, ty = threadIdx.y;   // 32 x 8
    const float* xb = x  + (size_t)b * kC * kHW;
    __nv_bfloat16* hb = hT + (size_t)b * kHW * kC;

    #pragma unroll
    for (int r = 0; r < 4; r++) {
        const int c = c0 + ty + r * 8;
        const float a  = aff[((size_t)b * kC + c) * 2 + 0];
        const float bb = aff[((size_t)b * kC + c) * 2 + 1];
        t[ty + r * 8][tx] = xb[(size_t)c * kHW + n0 + tx] * a + bb;
    }
    __syncthreads();
    #pragma unroll
    for (int r = 0; r < 4; r++) {
        const int n = n0 + ty + r * 8;
        hb[(size_t)n * kC + c0 + tx] = __float2bfloat16_rn(t[tx][ty + r * 8]);
    }
}

// ---------------------------------------------------------------------------
// bf16 mma.sync GEMM: C[m][n] = sum_k A[m][k] * B[n][k]  (both K-major bf16)
// CTA tile 128x256, 512 threads, 16 warps (2x8), warp tile 64x32.
// BK=16, 4 stages (12KB each = 48KB static), barrier every 2 k-steps,
// paired-stage commit groups (2-iteration prefetch lead).
// EPI: 0=+bias[n]->bf16, 1=+bias[m]->bf16,
//      2=exp2(alpha*acc)->bf16 + atomic row-sum into res (softmax numerator),
//      4=+bias[m]+res[m][n]->f32,
//      5=acc/rowsum[m]->bf16 (bias = rowsum base, per-batch kHW stride)
// ---------------------------------------------------------------------------
constexpr int kRowW   = 8;                // words per tile row (16 bf16 = BK)
constexpr int kTileWA = 128 * kRowW;      // 1024 words = 4 KB
constexpr int kTileWB = 256 * kRowW;      // 2048 words = 8 KB
constexpr int kStageW = kTileWA + kTileWB;// 3072 words = 12 KB
constexpr int kNS     = 4;                // stages (48 KB total)

__device__ __forceinline__ uint32_t swoff(int row, int c) {
    // word offset of 16B chunk c (0..1) in swizzled tile (row = 32B)
    return (uint32_t)(row * kRowW + ((c ^ ((row >> 2) & 1)) << 2));
}

template <int EPI>
__global__ void __launch_bounds__(512, 1)
gemm_bf16(const __nv_bfloat16* __restrict__ A, const __nv_bfloat16* __restrict__ B,
          const float* __restrict__ bias, float* __restrict__ res,
          void* __restrict__ Cv,
          int lda, int ldb, int ldc, int K,
          size_t sA, size_t sB, size_t sC, float alpha) {
    __shared__ __align__(16) uint32_t sm[kNS * kStageW];   // 49,152 bytes
    const int tid = threadIdx.x;
    const int lane = tid & 31, wid = tid >> 5;
    const int wm = wid & 1, wn = wid >> 1;   // warp grid 2 x 8

    const int bz = blockIdx.z;
    const __nv_bfloat16* Ab = A + sA * bz;
    const __nv_bfloat16* Bb = B + sB * bz;
    const int m0 = blockIdx.y * 128;
    const int n0 = blockIdx.x * 256;

    const uint32_t smAddr = smem_u32(sm);
    const int KT = K / 16;                    // even for all our K

    // ldmatrix lane decomposition (mapping verified in Round 7)
    const int lg   = lane >> 3;               // lane group 0..3
    const int lrow = lane & 7;
    const int aRow = wm * 64 + (lg & 1) * 8 + lrow;   // + mt*16
    const int aChk = lg >> 1;                          // chunk 0/1 = k16
    const int bRow = wn * 32 + (lg >> 1) * 8 + lrow;  // + j*16
    const int bChk = lg & 1;

    // prefetch k-block it into stage s
    auto prefetch = [&](int it, int s) {
        const int k0 = it * 16;
        const uint32_t aBase = smAddr + (uint32_t)(s * kStageW) * 4u;
        const uint32_t bBase = aBase + (uint32_t)kTileWA * 4u;
        const int row = tid >> 1, c = tid & 1;
        if (tid < 256)
            cp16(aBase + swoff(row, c) * 4u,
                 Ab + (size_t)(m0 + row) * lda + k0 + c * 8);
        cp16(bBase + swoff(row, c) * 4u,
             Bb + (size_t)(n0 + row) * ldb + k0 + c * 8);
    };

    float acc[4][4][4];
    #pragma unroll
    for (int i = 0; i < 4; i++)
        #pragma unroll
        for (int j = 0; j < 4; j++)
            #pragma unroll
            for (int r = 0; r < 4; r++) acc[i][j][r] = 0.f;

    prefetch(0, 0);
    prefetch(1, 1);
    cp_commit();                              // one group covers 2 stages

    for (int it = 0; it < KT; it += 2) {
        cp_wait<0>();                         // stages it, it+1 resident
        __syncthreads();                      // everyone done with it-2, it-1

        if (it + 2 < KT) {                    // KT even -> it+3 < KT too
            prefetch(it + 2, (it + 2) & 3);
            prefetch(it + 3, (it + 3) & 3);
            cp_commit();
        }

        #pragma unroll
        for (int j = 0; j < 2; j++) {
            const uint32_t aTile =
                smAddr + (uint32_t)(((it + j) & 3) * kStageW) * 4u;
            const uint32_t bTile = aTile + (uint32_t)kTileWA * 4u;

            uint32_t af[4][4];
            #pragma unroll
            for (int mt = 0; mt < 4; mt++)
                ldsm4(af[mt], aTile + swoff(aRow + mt * 16, aChk) * 4u);
            uint32_t bf[4][2];
            #pragma unroll
            for (int jb = 0; jb < 2; jb++)
                ldsm4(&bf[2 * jb][0], bTile + swoff(bRow + jb * 16, bChk) * 4u);

            #pragma unroll
            for (int mt = 0; mt < 4; mt++)
                #pragma unroll
                for (int nt = 0; nt < 4; nt++)
                    mma16(acc[mt][nt], af[mt], bf[nt]);
        }
    }

    // ---- epilogue ----
    const int rA = lane >> 2, cA = lane & 3;

    if constexpr (EPI == 2) {
        // exp2(alpha * acc) -> bf16 P~; atomic row-sum of rounded values
        __nv_bfloat16* Cb = (__nv_bfloat16*)Cv + sC * bz;
        float* rs = res + (size_t)bz * kHW;
        #pragma unroll
        for (int mt = 0; mt < 4; mt++) {
            const int r0 = m0 + wm * 64 + mt * 16 + rA;
            float s0 = 0.f, s1 = 0.f;
            #pragma unroll
            for (int nt = 0; nt < 4; nt++) {
                const int col = n0 + wn * 32 + nt * 8 + cA * 2;
                const float e0 = exp2f(acc[mt][nt][0] * alpha);
                const float e1 = exp2f(acc[mt][nt][1] * alpha);
                const float e2 = exp2f(acc[mt][nt][2] * alpha);
                const float e3 = exp2f(acc[mt][nt][3] * alpha);
                const __nv_bfloat162 w0 = __floats2bfloat162_rn(e0, e1);
                const __nv_bfloat162 w1 = __floats2bfloat162_rn(e2, e3);
                *(__nv_bfloat162*)(Cb + (size_t)r0 * ldc + col)       = w0;
                *(__nv_bfloat162*)(Cb + (size_t)(r0 + 8) * ldc + col) = w1;
                s0 += __low2float(w0) + __high2float(w0);
                s1 += __low2float(w1) + __high2float(w1);
            }
            s0 += __shfl_xor_sync(0xffffffffu, s0, 1);
            s0 += __shfl_xor_sync(0xffffffffu, s0, 2);
            s1 += __shfl_xor_sync(0xffffffffu, s1, 1);
            s1 += __shfl_xor_sync(0xffffffffu, s1, 2);
            if (cA == 0) {
                atomicAdd(&rs[r0], s0);
                atomicAdd(&rs[r0 + 8], s1);
            }
        }
        return;
    }

    constexpr bool OUTB = (EPI == 0 || EPI == 1 || EPI == 5);
    #pragma unroll
    for (int mt = 0; mt < 4; mt++) {
        const int r0 = m0 + wm * 64 + mt * 16 + rA;
        float bm0 = 0.f, bm1 = 0.f;
        if (EPI == 1 || EPI == 4) { bm0 = bias[r0]; bm1 = bias[r0 + 8]; }
        if (EPI == 5) {
            bm0 = 1.f / bias[(size_t)bz * kHW + r0];
            bm1 = 1.f / bias[(size_t)bz * kHW + r0 + 8];
        }
        #pragma unroll
        for (int nt = 0; nt < 4; nt++) {
            const int col = n0 + wn * 32 + nt * 8 + cA * 2;
            float d0 = acc[mt][nt][0], d1 = acc[mt][nt][1];
            float d2 = acc[mt][nt][2], d3 = acc[mt][nt][3];
            if (EPI == 0) {
                const float b0 = bias[col], b1 = bias[col + 1];
                d0 += b0; d1 += b1; d2 += b0; d3 += b1;
            } else if (EPI == 1 || EPI == 4) {
                d0 += bm0; d1 += bm0; d2 += bm1; d3 += bm1;
            } else if (EPI == 5) {
                d0 *= bm0; d1 *= bm0; d2 *= bm1; d3 *= bm1;
            }
            if (EPI == 4) {
                const float* rp = res + sC * bz;
                d0 += rp[(size_t)r0 * ldc + col];
                d1 += rp[(size_t)r0 * ldc + col + 1];
                d2 += rp[(size_t)(r0 + 8) * ldc + col];
                d3 += rp[(size_t)(r0 + 8) * ldc + col + 1];
            }
            if (OUTB) {
                __nv_bfloat16* Cb = (__nv_bfloat16*)Cv + sC * bz;
                *(__nv_bfloat162*)(Cb + (size_t)r0 * ldc + col) =
                    __floats2bfloat162_rn(d0, d1);
                *(__nv_bfloat162*)(Cb + (size_t)(r0 + 8) * ldc + col) =
                    __floats2bfloat162_rn(d2, d3);
            } else {
                float* Cb = (float*)Cv + sC * bz;
                *(float2*)(Cb + (size_t)r0 * ldc + col)       = make_float2(d0, d1);
                *(float2*)(Cb + (size_t)(r0 + 8) * ldc + col) = make_float2(d2, d3);
            }
        }
    }
}

// ---------------------------------------------------------------------------
extern "C" void kernel_launch(void* const* d_in, const int* in_sizes, int n_in,
                              void* d_out, int out_size) {
    const float* x     = (const float*)d_in[0];
    const float* gamma = (const float*)d_in[1];
    const float* beta  = (const float*)d_in[2];
    const float* wq    = (const float*)d_in[3];
    const float* bq    = (const float*)d_in[4];
    const float* wk    = (const float*)d_in[5];
    const float* bk    = (const float*)d_in[6];
    const float* wv    = (const float*)d_in[7];
    const float* bv    = (const float*)d_in[8];
    const float* wo    = (const float*)d_in[9];
    const float* bo    = (const float*)d_in[10];
    float* out = (float*)d_out;

    __nv_bfloat16 *hT, *qkt, *v, *o2, *simh, *wh;
    float *aff, *rs, *bqk;
    cudaGetSymbolAddress((void**)&hT,   g_hT);
    cudaGetSymbolAddress((void**)&qkt,  g_qkt);
    cudaGetSymbolAddress((void**)&v,    g_v);
    cudaGetSymbolAddress((void**)&o2,   g_o2);
    cudaGetSymbolAddress((void**)&simh, g_simh);
    cudaGetSymbolAddress((void**)&aff,  g_aff);
    cudaGetSymbolAddress((void**)&rs,   g_rs);
    cudaGetSymbolAddress((void**)&wh,   g_wh);
    cudaGetSymbolAddress((void**)&bqk,  g_bqk);

    const size_t sNC = (size_t)kHW * kC;      // per-batch [n][c] / [c][n]
    const size_t sQK = (size_t)kHW * 1024;    // per-batch [n][1024]
    const size_t sNN = (size_t)kHW * kHW;     // per-batch sim
    const float  scale  = 1.0f / sqrtf((float)kC);
    const float  scale2 = scale * 1.4426950408889634f;   // fold log2(e)
    const int nW = kC * kC;

    // 0) weights -> bf16 (+ concat q/k bias); zero row sums
    prep_weights<<<(nW + 255) / 256, 256>>>(wq, wk, wv, wo, bq, bk, wh, bqk);
    rs_init<<<kB * kHW / 256, 256>>>(rs);

    // 1) GroupNorm (stats + fused normalize-transpose-bf16)
    gn_stats<<<kB * kG, 256>>>(x, gamma, beta, aff);
    gn_norm_t<<<dim3(kHW / 32, kC / 32, kB), dim3(32, 8)>>>(x, aff, hT);

    // 2) [Q|K]^T = hT @ [Wq;Wk]^T  (M=4096, N=1024, K=512), bias over columns
    {
        dim3 grid(1024 / 256, kHW / 128, kB);
        gemm_bf16<0><<<grid, 512>>>(hT, wh, bqk, nullptr, qkt,
                                    kC, kC, 1024, kC, sNC, 0, sQK, 1.f);
    }
    // 3) V = Wv @ H  (M=512, N=4096, K=512), output [c][n], bias over rows
    {
        dim3 grid(kHW / 256, kC / 128, kB);
        gemm_bf16<1><<<grid, 512>>>(wh + 2 * nW, hT, bv, nullptr, v,
                                    kC, kC, kHW, kC, 0, sNC, sNC, 1.f);
    }
    // 4) P~ = exp2(scale2 * Qt@Kt^T) -> bf16, + row sums (M=N=4096, K=512)
    {
        dim3 grid(kHW / 256, kHW / 128, kB);
        gemm_bf16<2><<<grid, 512>>>(qkt, qkt + 512, nullptr, rs, simh,
                                    1024, 1024, kHW, kC, sQK, sQK, sNN, scale2);
    }
    // 5) o2 = (P~ @ V^T) / rowsum  (M=4096, N=512, K=4096), output [n][c] bf16
    {
        dim3 grid(kC / 256, kHW / 128, kB);
        gemm_bf16<5><<<grid, 512>>>(simh, v, rs, nullptr, o2,
                                    kHW, kHW, kC, kHW, sNN, sNC, sNC, 1.f);
    }
    // 6) out = x + Wo @ o2^T + bo  (M=512, N=4096, K=512), f32 out
    {
        dim3 grid(kHW / 256, kC / 128, kB);
        gemm_bf16<4><<<grid, 512>>>(wh + 3 * nW, o2, bo, (float*)x, out,
                                    kC, kC, kHW, kC, 0, sNC, sNC, 1.f);
    }
}

// round 12
// speedup vs baseline: 1.2740x; 1.2740x over previous
#include <cuda_runtime.h>
#include <cuda_bf16.h>
#include <cstdint>
#include <math.h>

// ---------------------------------------------------------------------------
// Problem constants
// ---------------------------------------------------------------------------
constexpr int kB  = 4;
constexpr int kC  = 512;
constexpr int kHW = 4096;
constexpr int kG  = 32;
constexpr int kCPG = kC / kG;   // 16
constexpr float kEPS = 1e-6f;

// Scratch (__device__ globals per allocation-free rule)
__device__ __nv_bfloat16 g_hT  [(size_t)kB * kHW * kC];    // GN out [b][n][c]
__device__ __nv_bfloat16 g_qkt [(size_t)kB * kHW * 1024];  // [b][n][q||k]
__device__ __nv_bfloat16 g_v   [(size_t)kB * kC * kHW];    // V [b][c][n]
__device__ __nv_bfloat16 g_o2  [(size_t)kB * kHW * kC];    // attn@V [b][n][c]
__device__ __nv_bfloat16 g_simh[(size_t)kB * kHW * kHW];   // P~ bf16 (128 MB)
__device__ float         g_rs  [(size_t)kB * kHW];         // softmax row sums
__device__ float         g_aff [(size_t)kB * kC * 2];      // (scale, offset)
__device__ __nv_bfloat16 g_wh  [4 * kC * kC];              // bf16 wq,wk,wv,wo
__device__ float         g_bqk [2 * kC];                   // bq || bk

// ---------------------------------------------------------------------------
// Helpers
// ---------------------------------------------------------------------------
__device__ __forceinline__ uint32_t smem_u32(const void* p) {
    uint32_t a;
    asm("{ .reg .u64 t; cvta.to.shared.u64 t, %1; cvt.u32.u64 %0, t; }"
        : "=r"(a) : "l"(p));
    return a;
}
__device__ __forceinline__ void cp16(uint32_t dst, const void* src) {
    asm volatile("cp.async.cg.shared.global [%0], [%1], 16;\n"
                 :: "r"(dst), "l"(src));
}
__device__ __forceinline__ void cp_commit() {
    asm volatile("cp.async.commit_group;\n" ::: "memory");
}
template <int N>
__device__ __forceinline__ void cp_wait() {
    asm volatile("cp.async.wait_group %0;\n" :: "n"(N) : "memory");
}
// m16n8k16 bf16 mma, row.col, fp32 accum
__device__ __forceinline__ void mma16(float* d, const uint32_t* a, const uint32_t* b) {
    asm volatile(
        "mma.sync.aligned.m16n8k16.row.col.f32.bf16.bf16.f32 "
        "{%0,%1,%2,%3}, {%4,%5,%6,%7}, {%8,%9}, {%0,%1,%2,%3};"
        : "+f"(d[0]), "+f"(d[1]), "+f"(d[2]), "+f"(d[3])
        : "r"(a[0]), "r"(a[1]), "r"(a[2]), "r"(a[3]), "r"(b[0]), "r"(b[1]));
}
// ldmatrix 4x (m8n8 b16)
__device__ __forceinline__ void ldsm4(uint32_t* r, uint32_t addr) {
    asm volatile(
        "ldmatrix.sync.aligned.m8n8.x4.shared.b16 {%0,%1,%2,%3}, [%4];"
        : "=r"(r[0]), "=r"(r[1]), "=r"(r[2]), "=r"(r[3]) : "r"(addr));
}

// ---------------------------------------------------------------------------
// Weight prep: bf16 weights + concatenated q/k bias
// ---------------------------------------------------------------------------
__global__ void prep_weights(const float* __restrict__ wq, const float* __restrict__ wk,
                             const float* __restrict__ wv, const float* __restrict__ wo,
                             const float* __restrict__ bq, const float* __restrict__ bk,
                             __nv_bfloat16* __restrict__ wh, float* __restrict__ bqk) {
    const int i = blockIdx.x * blockDim.x + threadIdx.x;
    const int n = kC * kC;
    if (i < n) {
        wh[0 * n + i] = __float2bfloat16_rn(wq[i]);
        wh[1 * n + i] = __float2bfloat16_rn(wk[i]);
        wh[2 * n + i] = __float2bfloat16_rn(wv[i]);
        wh[3 * n + i] = __float2bfloat16_rn(wo[i]);
    }
    if (i < kC)          bqk[i] = bq[i];
    else if (i < 2 * kC) bqk[i] = bk[i - kC];
}

// Zero the softmax row-sum accumulators (graph-replay safe)
__global__ void rs_init(float* __restrict__ rs) {
    rs[blockIdx.x * 256 + threadIdx.x] = 0.f;
}

// ---------------------------------------------------------------------------
// GroupNorm pass 1: per-(b,g) mean/var -> per-channel affine (a, b)
// ---------------------------------------------------------------------------
__global__ void gn_stats(const float* __restrict__ x,
                         const float* __restrict__ gamma,
                         const float* __restrict__ beta,
                         float* __restrict__ aff) {
    const int b = blockIdx.x / kG, g = blockIdx.x % kG;
    const float* xp = x + ((size_t)b * kC + (size_t)g * kCPG) * kHW;
    const int N = kCPG * kHW;

    float s = 0.f, ss = 0.f;
    for (int i = threadIdx.x; i < N; i += 256) {
        float v = xp[i];
        s += v; ss += v * v;
    }
    __shared__ float sh1[256], sh2[256];
    sh1[threadIdx.x] = s; sh2[threadIdx.x] = ss;
    __syncthreads();
    for (int o = 128; o > 0; o >>= 1) {
        if (threadIdx.x < o) {
            sh1[threadIdx.x] += sh1[threadIdx.x + o];
            sh2[threadIdx.x] += sh2[threadIdx.x + o];
        }
        __syncthreads();
    }
    if (threadIdx.x < kCPG) {
        const float mean = sh1[0] / (float)N;
        const float var  = sh2[0] / (float)N - mean * mean;
        const float rinv = rsqrtf(var + kEPS);
        const int ch = g * kCPG + threadIdx.x;
        const float a = rinv * gamma[ch];
        aff[((size_t)b * kC + ch) * 2 + 0] = a;
        aff[((size_t)b * kC + ch) * 2 + 1] = beta[ch] - mean * a;
    }
}

// ---------------------------------------------------------------------------
// GroupNorm pass 2: normalize + transpose + bf16: x[b][c][n] -> hT[b][n][c]
// ---------------------------------------------------------------------------
__global__ void gn_norm_t(const float* __restrict__ x,
                          const float* __restrict__ aff,
                          __nv_bfloat16* __restrict__ hT) {
    __shared__ float t[32][33];
    const int b = blockIdx.z;
    const int n0 = blockIdx.x * 32, c0 = blockIdx.y * 32;
    const int tx = threadIdx.x, ty = threadIdx.y;   // 32 x 8
    const float* xb = x  + (size_t)b * kC * kHW;
    __nv_bfloat16* hb = hT + (size_t)b * kHW * kC;

    #pragma unroll
    for (int r = 0; r < 4; r++) {
        const int c = c0 + ty + r * 8;
        const float a  = aff[((size_t)b * kC + c) * 2 + 0];
        const float bb = aff[((size_t)b * kC + c) * 2 + 1];
        t[ty + r * 8][tx] = xb[(size_t)c * kHW + n0 + tx] * a + bb;
    }
    __syncthreads();
    #pragma unroll
    for (int r = 0; r < 4; r++) {
        const int n = n0 + ty + r * 8;
        hb[(size_t)n * kC + c0 + tx] = __float2bfloat16_rn(t[tx][ty + r * 8]);
    }
}

// ---------------------------------------------------------------------------
// bf16 mma.sync GEMM: C[m][n] = sum_k A[m][k] * B[n][k]  (both K-major bf16)
// 128x128x32 tile, 3-stage cp.async pipeline (lead 2), swizzled smem, 48KB.
// 256 threads, 8 warps (2x4), warp tile 64x32. 2 CTAs/SM.
// (This is the verified Round-9/10 mainloop, unchanged.)
// EPI: 0=+bias[n]->bf16, 1=+bias[m]->bf16,
//      2=exp2(alpha*acc)->bf16 + atomic row-sum into res (softmax numerator),
//      4=+bias[m]+res[m][n]->f32,
//      5=acc/rowsum[m]->bf16 (bias = rowsum base, per-batch kHW stride)
// ---------------------------------------------------------------------------
constexpr int kRowW   = 16;              // words per tile row (32 bf16)
constexpr int kTileW  = 128 * kRowW;     // 2048 words = 8 KB per tile
constexpr int kStageW = 2 * kTileW;      // A + B = 16 KB per stage
constexpr int kNS     = 3;               // stages (48 KB total)

__device__ __forceinline__ uint32_t swoff(int row, int c) {
    // word offset of 16B chunk c in swizzled tile (row = 64B)
    return (uint32_t)(row * kRowW + ((c ^ ((row >> 1) & 3)) << 2));
}

template <int EPI>
__global__ void __launch_bounds__(256, 2)
gemm_bf16(const __nv_bfloat16* __restrict__ A, const __nv_bfloat16* __restrict__ B,
          const float* __restrict__ bias, float* __restrict__ res,
          void* __restrict__ Cv,
          int lda, int ldb, int ldc, int K,
          size_t sA, size_t sB, size_t sC, float alpha) {
    __shared__ __align__(16) uint32_t sm[kNS * kStageW];   // 49,152 bytes
    const int tid = threadIdx.x;
    const int lane = tid & 31, wid = tid >> 5;
    const int wm = wid & 1, wn = wid >> 1;   // warp grid 2 x 4

    const int bz = blockIdx.z;
    const __nv_bfloat16* Ab = A + sA * bz;
    const __nv_bfloat16* Bb = B + sB * bz;
    const int m0 = blockIdx.y * 128;
    const int n0 = blockIdx.x * 128;

    const uint32_t smAddr = smem_u32(sm);
    const int KT = K / 32;

    // ldmatrix lane decomposition (mapping verified in Round 7)
    const int lg   = lane >> 3;          // lane group 0..3
    const int lrow = lane & 7;
    const int aRow = wm * 64 + (lg & 1) * 8 + lrow;   // + mt*16
    const int aChk = lg >> 1;                          // + kk*2
    const int bRow = wn * 32 + (lg >> 1) * 8 + lrow;  // + j*16
    const int bChk = lg & 1;                           // + kk*2

    // prefetch k-block it into stage s: 4 cp16 per thread (2 A + 2 B)
    auto prefetch = [&](int it, int s) {
        const int k0 = it * 32;
        const uint32_t aBase = smAddr + (uint32_t)(s * kStageW) * 4u;
        const uint32_t bBase = aBase + (uint32_t)kTileW * 4u;
        #pragma unroll
        for (int t = 0; t < 2; t++) {
            const int idx = t * 256 + tid;   // 0..511
            const int row = idx >> 2, c = idx & 3;
            const uint32_t off = swoff(row, c) * 4u;
            cp16(aBase + off, Ab + (size_t)(m0 + row) * lda + k0 + c * 8);
            cp16(bBase + off, Bb + (size_t)(n0 + row) * ldb + k0 + c * 8);
        }
    };

    float acc[4][4][4];
    #pragma unroll
    for (int i = 0; i < 4; i++)
        #pragma unroll
        for (int j = 0; j < 4; j++)
            #pragma unroll
            for (int r = 0; r < 4; r++) acc[i][j][r] = 0.f;

    prefetch(0, 0); cp_commit();
    prefetch(1, 1); cp_commit();

    for (int it = 0; it < KT; ++it) {
        cp_wait<1>();                // stage it%3 resident
        __syncthreads();             // all warps done reading stage (it+2)%3

        if (it + 2 < KT) prefetch(it + 2, (it + 2) % kNS);
        cp_commit();

        const uint32_t aTile = smAddr + (uint32_t)((it % kNS) * kStageW) * 4u;
        const uint32_t bTile = aTile + (uint32_t)kTileW * 4u;

        #pragma unroll
        for (int kk = 0; kk < 2; kk++) {
            uint32_t af[4][4];
            #pragma unroll
            for (int mt = 0; mt < 4; mt++)
                ldsm4(af[mt], aTile +
                      swoff(aRow + mt * 16, aChk + kk * 2) * 4u);
            uint32_t bf[4][2];
            #pragma unroll
            for (int j = 0; j < 2; j++)
                ldsm4(&bf[2 * j][0], bTile +
                      swoff(bRow + j * 16, bChk + kk * 2) * 4u);
            #pragma unroll
            for (int mt = 0; mt < 4; mt++)
                #pragma unroll
                for (int nt = 0; nt < 4; nt++)
                    mma16(acc[mt][nt], af[mt], bf[nt]);
        }
    }

    // ---- epilogue ----
    const int rA = lane >> 2, cA = lane & 3;

    if constexpr (EPI == 2) {
        // exp2(alpha * acc) -> bf16 P~; atomic row-sum of rounded values
        __nv_bfloat16* Cb = (__nv_bfloat16*)Cv + sC * bz;
        float* rs = res + (size_t)bz * kHW;
        #pragma unroll
        for (int mt = 0; mt < 4; mt++) {
            const int r0 = m0 + wm * 64 + mt * 16 + rA;
            float s0 = 0.f, s1 = 0.f;
            #pragma unroll
            for (int nt = 0; nt < 4; nt++) {
                const int col = n0 + wn * 32 + nt * 8 + cA * 2;
                const float e0 = exp2f(acc[mt][nt][0] * alpha);
                const float e1 = exp2f(acc[mt][nt][1] * alpha);
                const float e2 = exp2f(acc[mt][nt][2] * alpha);
                const float e3 = exp2f(acc[mt][nt][3] * alpha);
                const __nv_bfloat162 w0 = __floats2bfloat162_rn(e0, e1);
                const __nv_bfloat162 w1 = __floats2bfloat162_rn(e2, e3);
                *(__nv_bfloat162*)(Cb + (size_t)r0 * ldc + col)       = w0;
                *(__nv_bfloat162*)(Cb + (size_t)(r0 + 8) * ldc + col) = w1;
                s0 += __low2float(w0) + __high2float(w0);
                s1 += __low2float(w1) + __high2float(w1);
            }
            s0 += __shfl_xor_sync(0xffffffffu, s0, 1);
            s0 += __shfl_xor_sync(0xffffffffu, s0, 2);
            s1 += __shfl_xor_sync(0xffffffffu, s1, 1);
            s1 += __shfl_xor_sync(0xffffffffu, s1, 2);
            if (cA == 0) {
                atomicAdd(&rs[r0], s0);
                atomicAdd(&rs[r0 + 8], s1);
            }
        }
        return;
    }

    constexpr bool OUTB = (EPI == 0 || EPI == 1 || EPI == 5);
    #pragma unroll
    for (int mt = 0; mt < 4; mt++) {
        const int r0 = m0 + wm * 64 + mt * 16 + rA;
        float bm0 = 0.f, bm1 = 0.f;
        if (EPI == 1 || EPI == 4) { bm0 = bias[r0]; bm1 = bias[r0 + 8]; }
        if (EPI == 5) {
            bm0 = 1.f / bias[(size_t)bz * kHW + r0];
            bm1 = 1.f / bias[(size_t)bz * kHW + r0 + 8];
        }
        #pragma unroll
        for (int nt = 0; nt < 4; nt++) {
            const int col = n0 + wn * 32 + nt * 8 + cA * 2;
            float d0 = acc[mt][nt][0], d1 = acc[mt][nt][1];
            float d2 = acc[mt][nt][2], d3 = acc[mt][nt][3];
            if (EPI == 0) {
                const float b0 = bias[col], b1 = bias[col + 1];
                d0 += b0; d1 += b1; d2 += b0; d3 += b1;
            } else if (EPI == 1 || EPI == 4) {
                d0 += bm0; d1 += bm0; d2 += bm1; d3 += bm1;
            } else if (EPI == 5) {
                d0 *= bm0; d1 *= bm0; d2 *= bm1; d3 *= bm1;
            }
            if (EPI == 4) {
                const float* rp = res + sC * bz;
                d0 += rp[(size_t)r0 * ldc + col];
                d1 += rp[(size_t)r0 * ldc + col + 1];
                d2 += rp[(size_t)(r0 + 8) * ldc + col];
                d3 += rp[(size_t)(r0 + 8) * ldc + col + 1];
            }
            if (OUTB) {
                __nv_bfloat16* Cb = (__nv_bfloat16*)Cv + sC * bz;
                *(__nv_bfloat162*)(Cb + (size_t)r0 * ldc + col) =
                    __floats2bfloat162_rn(d0, d1);
                *(__nv_bfloat162*)(Cb + (size_t)(r0 + 8) * ldc + col) =
                    __floats2bfloat162_rn(d2, d3);
            } else {
                float* Cb = (float*)Cv + sC * bz;
                *(float2*)(Cb + (size_t)r0 * ldc + col)       = make_float2(d0, d1);
                *(float2*)(Cb + (size_t)(r0 + 8) * ldc + col) = make_float2(d2, d3);
            }
        }
    }
}

// ---------------------------------------------------------------------------
extern "C" void kernel_launch(void* const* d_in, const int* in_sizes, int n_in,
                              void* d_out, int out_size) {
    const float* x     = (const float*)d_in[0];
    const float* gamma = (const float*)d_in[1];
    const float* beta  = (const float*)d_in[2];
    const float* wq    = (const float*)d_in[3];
    const float* bq    = (const float*)d_in[4];
    const float* wk    = (const float*)d_in[5];
    const float* bk    = (const float*)d_in[6];
    const float* wv    = (const float*)d_in[7];
    const float* bv    = (const float*)d_in[8];
    const float* wo    = (const float*)d_in[9];
    const float* bo    = (const float*)d_in[10];
    float* out = (float*)d_out;

    __nv_bfloat16 *hT, *qkt, *v, *o2, *simh, *wh;
    float *aff, *rs, *bqk;
    cudaGetSymbolAddress((void**)&hT,   g_hT);
    cudaGetSymbolAddress((void**)&qkt,  g_qkt);
    cudaGetSymbolAddress((void**)&v,    g_v);
    cudaGetSymbolAddress((void**)&o2,   g_o2);
    cudaGetSymbolAddress((void**)&simh, g_simh);
    cudaGetSymbolAddress((void**)&aff,  g_aff);
    cudaGetSymbolAddress((void**)&rs,   g_rs);
    cudaGetSymbolAddress((void**)&wh,   g_wh);
    cudaGetSymbolAddress((void**)&bqk,  g_bqk);

    const size_t sNC = (size_t)kHW * kC;      // per-batch [n][c] / [c][n]
    const size_t sQK = (size_t)kHW * 1024;    // per-batch [n][1024]
    const size_t sNN = (size_t)kHW * kHW;     // per-batch sim
    const float  scale  = 1.0f / sqrtf((float)kC);
    const float  scale2 = scale * 1.4426950408889634f;   // fold log2(e)
    const int nW = kC * kC;

    // 0) weights -> bf16 (+ concat q/k bias); zero row sums
    prep_weights<<<(nW + 255) / 256, 256>>>(wq, wk, wv, wo, bq, bk, wh, bqk);
    rs_init<<<kB * kHW / 256, 256>>>(rs);

    // 1) GroupNorm (stats + fused normalize-transpose-bf16)
    gn_stats<<<kB * kG, 256>>>(x, gamma, beta, aff);
    gn_norm_t<<<dim3(kHW / 32, kC / 32, kB), dim3(32, 8)>>>(x, aff, hT);

    // 2) [Q|K]^T = hT @ [Wq;Wk]^T  (M=4096, N=1024, K=512), bias over columns
    {
        dim3 grid(1024 / 128, kHW / 128, kB);
        gemm_bf16<0><<<grid, 256>>>(hT, wh, bqk, nullptr, qkt,
                                    kC, kC, 1024, kC, sNC, 0, sQK, 1.f);
    }
    // 3) V = Wv @ H  (M=512, N=4096, K=512), output [c][n], bias over rows
    {
        dim3 grid(kHW / 128, kC / 128, kB);
        gemm_bf16<1><<<grid, 256>>>(wh + 2 * nW, hT, bv, nullptr, v,
                                    kC, kC, kHW, kC, 0, sNC, sNC, 1.f);
    }
    // 4) P~ = exp2(scale2 * Qt@Kt^T) -> bf16, + row sums (M=N=4096, K=512)
    {
        dim3 grid(kHW / 128, kHW / 128, kB);
        gemm_bf16<2><<<grid, 256>>>(qkt, qkt + 512, nullptr, rs, simh,
                                    1024, 1024, kHW, kC, sQK, sQK, sNN, scale2);
    }
    // 5) o2 = (P~ @ V^T) / rowsum  (M=4096, N=512, K=4096), output [n][c] bf16
    {
        dim3 grid(kC / 128, kHW / 128, kB);
        gemm_bf16<5><<<grid, 256>>>(simh, v, rs, nullptr, o2,
                                    kHW, kHW, kC, kHW, sNN, sNC, sNC, 1.f);
    }
    // 6) out = x + Wo @ o2^T + bo  (M=512, N=4096, K=512), f32 out
    {
        dim3 grid(kHW / 128, kC / 128, kB);
        gemm_bf16<4><<<grid, 256>>>(wh + 3 * nW, o2, bo, (float*)x, out,
                                    kC, kC, kHW, kC, 0, sNC, sNC, 1.f);
    }
}

// round 13
// speedup vs baseline: 1.2962x; 1.0174x over previous
#include <cuda_runtime.h>
#include <cuda_bf16.h>
#include <cstdint>
#include <math.h>

// ---------------------------------------------------------------------------
// Problem constants
// ---------------------------------------------------------------------------
constexpr int kB  = 4;
constexpr int kC  = 512;
constexpr int kHW = 4096;
constexpr int kG  = 32;
constexpr int kCPG = kC / kG;   // 16
constexpr float kEPS = 1e-6f;

// Scratch (__device__ globals per allocation-free rule)
__device__ __nv_bfloat16 g_hT  [(size_t)kB * kHW * kC];    // GN out [b][n][c]
__device__ __nv_bfloat16 g_qkt [(size_t)kB * kHW * 1024];  // [b][n][q||k]
__device__ __nv_bfloat16 g_v   [(size_t)kB * kC * kHW];    // V [b][c][n]
__device__ __nv_bfloat16 g_o2  [(size_t)kB * kHW * kC];    // attn@V [b][n][c]
__device__ __nv_bfloat16 g_simh[(size_t)kB * kHW * kHW];   // P~ bf16 (128 MB)
__device__ float         g_rs  [(size_t)kB * kHW];         // softmax row sums
__device__ float         g_aff [(size_t)kB * kC * 2];      // (scale, offset)
__device__ __nv_bfloat16 g_wh  [4 * kC * kC];              // bf16 wq,wk,wv,wo
__device__ float         g_bqk [2 * kC];                   // bq || bk

// ---------------------------------------------------------------------------
// Helpers
// ---------------------------------------------------------------------------
__device__ __forceinline__ uint32_t smem_u32(const void* p) {
    uint32_t a;
    asm("{ .reg .u64 t; cvta.to.shared.u64 t, %1; cvt.u32.u64 %0, t; }"
        : "=r"(a) : "l"(p));
    return a;
}
__device__ __forceinline__ void cp16(uint32_t dst, const void* src) {
    asm volatile("cp.async.cg.shared.global [%0], [%1], 16;\n"
                 :: "r"(dst), "l"(src));
}
__device__ __forceinline__ void cp_commit() {
    asm volatile("cp.async.commit_group;\n" ::: "memory");
}
template <int N>
__device__ __forceinline__ void cp_wait() {
    asm volatile("cp.async.wait_group %0;\n" :: "n"(N) : "memory");
}
// m16n8k16 bf16 mma, row.col, fp32 accum
__device__ __forceinline__ void mma16(float* d, const uint32_t* a, const uint32_t* b) {
    asm volatile(
        "mma.sync.aligned.m16n8k16.row.col.f32.bf16.bf16.f32 "
        "{%0,%1,%2,%3}, {%4,%5,%6,%7}, {%8,%9}, {%0,%1,%2,%3};"
        : "+f"(d[0]), "+f"(d[1]), "+f"(d[2]), "+f"(d[3])
        : "r"(a[0]), "r"(a[1]), "r"(a[2]), "r"(a[3]), "r"(b[0]), "r"(b[1]));
}
// ldmatrix 4x (m8n8 b16)
__device__ __forceinline__ void ldsm4(uint32_t* r, uint32_t addr) {
    asm volatile(
        "ldmatrix.sync.aligned.m8n8.x4.shared.b16 {%0,%1,%2,%3}, [%4];"
        : "=r"(r[0]), "=r"(r[1]), "=r"(r[2]), "=r"(r[3]) : "r"(addr));
}

// ---------------------------------------------------------------------------
// Weight prep: bf16 weights + concatenated q/k bias
// ---------------------------------------------------------------------------
__global__ void prep_weights(const float* __restrict__ wq, const float* __restrict__ wk,
                             const float* __restrict__ wv, const float* __restrict__ wo,
                             const float* __restrict__ bq, const float* __restrict__ bk,
                             __nv_bfloat16* __restrict__ wh, float* __restrict__ bqk) {
    const int i = blockIdx.x * blockDim.x + threadIdx.x;
    const int n = kC * kC;
    if (i < n) {
        wh[0 * n + i] = __float2bfloat16_rn(wq[i]);
        wh[1 * n + i] = __float2bfloat16_rn(wk[i]);
        wh[2 * n + i] = __float2bfloat16_rn(wv[i]);
        wh[3 * n + i] = __float2bfloat16_rn(wo[i]);
    }
    if (i < kC)          bqk[i] = bq[i];
    else if (i < 2 * kC) bqk[i] = bk[i - kC];
}

// Zero the softmax row-sum accumulators (graph-replay safe)
__global__ void rs_init(float* __restrict__ rs) {
    rs[blockIdx.x * 256 + threadIdx.x] = 0.f;
}

// ---------------------------------------------------------------------------
// GroupNorm pass 1: per-(b,g) mean/var -> per-channel affine (a, b)
// ---------------------------------------------------------------------------
__global__ void gn_stats(const float* __restrict__ x,
                         const float* __restrict__ gamma,
                         const float* __restrict__ beta,
                         float* __restrict__ aff) {
    const int b = blockIdx.x / kG, g = blockIdx.x % kG;
    const float* xp = x + ((size_t)b * kC + (size_t)g * kCPG) * kHW;
    const int N = kCPG * kHW;

    float s = 0.f, ss = 0.f;
    for (int i = threadIdx.x; i < N; i += 256) {
        float v = xp[i];
        s += v; ss += v * v;
    }
    __shared__ float sh1[256], sh2[256];
    sh1[threadIdx.x] = s; sh2[threadIdx.x] = ss;
    __syncthreads();
    for (int o = 128; o > 0; o >>= 1) {
        if (threadIdx.x < o) {
            sh1[threadIdx.x] += sh1[threadIdx.x + o];
            sh2[threadIdx.x] += sh2[threadIdx.x + o];
        }
        __syncthreads();
    }
    if (threadIdx.x < kCPG) {
        const float mean = sh1[0] / (float)N;
        const float var  = sh2[0] / (float)N - mean * mean;
        const float rinv = rsqrtf(var + kEPS);
        const int ch = g * kCPG + threadIdx.x;
        const float a = rinv * gamma[ch];
        aff[((size_t)b * kC + ch) * 2 + 0] = a;
        aff[((size_t)b * kC + ch) * 2 + 1] = beta[ch] - mean * a;
    }
}

// ---------------------------------------------------------------------------
// GroupNorm pass 2: normalize + transpose + bf16: x[b][c][n] -> hT[b][n][c]
// ---------------------------------------------------------------------------
__global__ void gn_norm_t(const float* __restrict__ x,
                          const float* __restrict__ aff,
                          __nv_bfloat16* __restrict__ hT) {
    __shared__ float t[32][33];
    const int b = blockIdx.z;
    const int n0 = blockIdx.x * 32, c0 = blockIdx.y * 32;
    const int tx = threadIdx.x, ty = threadIdx.y;   // 32 x 8
    const float* xb = x  + (size_t)b * kC * kHW;
    __nv_bfloat16* hb = hT + (size_t)b * kHW * kC;

    #pragma unroll
    for (int r = 0; r < 4; r++) {
        const int c = c0 + ty + r * 8;
        const float a  = aff[((size_t)b * kC + c) * 2 + 0];
        const float bb = aff[((size_t)b * kC + c) * 2 + 1];
        t[ty + r * 8][tx] = xb[(size_t)c * kHW + n0 + tx] * a + bb;
    }
    __syncthreads();
    #pragma unroll
    for (int r = 0; r < 4; r++) {
        const int n = n0 + ty + r * 8;
        hb[(size_t)n * kC + c0 + tx] = __float2bfloat16_rn(t[tx][ty + r * 8]);
    }
}

// ---------------------------------------------------------------------------
// bf16 mma.sync GEMM: C[m][n] = sum_k A[m][k] * B[n][k]  (both K-major bf16)
// 128x128x32 tile, 3-stage cp.async pipeline (lead 2), swizzled smem, 48KB.
// 256 threads, 8 warps (2x4), warp tile 64x32. 2 CTAs/SM.
// NEW: register double-buffered fragments (LDSM for k-step kk+1 issued before
// the MMAs of kk) + hoisted prefetch addressing.
// EPI: 0=+bias[n]->bf16, 1=+bias[m]->bf16,
//      2=exp2(alpha*acc)->bf16 + atomic row-sum into res (softmax numerator),
//      4=+bias[m]+res[m][n]->f32,
//      5=acc/rowsum[m]->bf16 (bias = rowsum base, per-batch kHW stride)
// ---------------------------------------------------------------------------
constexpr int kRowW   = 16;              // words per tile row (32 bf16)
constexpr int kTileW  = 128 * kRowW;     // 2048 words = 8 KB per tile
constexpr int kStageW = 2 * kTileW;      // A + B = 16 KB per stage
constexpr int kNS     = 3;               // stages (48 KB total)

__device__ __forceinline__ uint32_t swoff(int row, int c) {
    // word offset of 16B chunk c in swizzled tile (row = 64B)
    return (uint32_t)(row * kRowW + ((c ^ ((row >> 1) & 3)) << 2));
}

template <int EPI>
__global__ void __launch_bounds__(256, 2)
gemm_bf16(const __nv_bfloat16* __restrict__ A, const __nv_bfloat16* __restrict__ B,
          const float* __restrict__ bias, float* __restrict__ res,
          void* __restrict__ Cv,
          int lda, int ldb, int ldc, int K,
          size_t sA, size_t sB, size_t sC, float alpha) {
    __shared__ __align__(16) uint32_t sm[kNS * kStageW];   // 49,152 bytes
    const int tid = threadIdx.x;
    const int lane = tid & 31, wid = tid >> 5;
    const int wm = wid & 1, wn = wid >> 1;   // warp grid 2 x 4

    const int bz = blockIdx.z;
    const int m0 = blockIdx.y * 128;
    const int n0 = blockIdx.x * 128;

    const uint32_t smAddr = smem_u32(sm);
    const int KT = K / 32;

    // ldmatrix lane decomposition (mapping verified in Round 7)
    const int lg   = lane >> 3;          // lane group 0..3
    const int lrow = lane & 7;
    const int aRow = wm * 64 + (lg & 1) * 8 + lrow;   // + mt*16
    const int aChk = lg >> 1;                          // + kk*2
    const int bRow = wn * 32 + (lg >> 1) * 8 + lrow;  // + j*16
    const int bChk = lg & 1;                           // + kk*2

    // ---- hoisted prefetch addressing (constant per thread except k0) ----
    const int pr0 = tid >> 2, pc0 = tid & 3;           // t=0
    const int pr1 = (256 + tid) >> 2, pc1 = (256 + tid) & 3;  // t=1
    const uint32_t pOff0 = swoff(pr0, pc0) * 4u;
    const uint32_t pOff1 = swoff(pr1, pc1) * 4u;
    const __nv_bfloat16* gA0 = A + sA * bz + (size_t)(m0 + pr0) * lda + pc0 * 8;
    const __nv_bfloat16* gA1 = A + sA * bz + (size_t)(m0 + pr1) * lda + pc1 * 8;
    const __nv_bfloat16* gB0 = B + sB * bz + (size_t)(n0 + pr0) * ldb + pc0 * 8;
    const __nv_bfloat16* gB1 = B + sB * bz + (size_t)(n0 + pr1) * ldb + pc1 * 8;

    auto prefetch = [&](int it, int s) {
        const int k0 = it * 32;
        const uint32_t aBase = smAddr + (uint32_t)(s * kStageW) * 4u;
        const uint32_t bBase = aBase + (uint32_t)kTileW * 4u;
        cp16(aBase + pOff0, gA0 + k0);
        cp16(aBase + pOff1, gA1 + k0);
        cp16(bBase + pOff0, gB0 + k0);
        cp16(bBase + pOff1, gB1 + k0);
    };

    float acc[4][4][4];
    #pragma unroll
    for (int i = 0; i < 4; i++)
        #pragma unroll
        for (int j = 0; j < 4; j++)
            #pragma unroll
            for (int r = 0; r < 4; r++) acc[i][j][r] = 0.f;

    prefetch(0, 0); cp_commit();
    prefetch(1, 1); cp_commit();

    uint32_t af[2][4][4];
    uint32_t bf[2][4][2];

    for (int it = 0; it < KT; ++it) {
        cp_wait<1>();                // stage it%3 resident
        __syncthreads();             // all warps done reading stage (it+2)%3

        if (it + 2 < KT) prefetch(it + 2, (it + 2) % kNS);
        cp_commit();

        const uint32_t aTile = smAddr + (uint32_t)((it % kNS) * kStageW) * 4u;
        const uint32_t bTile = aTile + (uint32_t)kTileW * 4u;

        // load fragments for k-step 0
        #pragma unroll
        for (int mt = 0; mt < 4; mt++)
            ldsm4(af[0][mt], aTile + swoff(aRow + mt * 16, aChk) * 4u);
        #pragma unroll
        for (int j = 0; j < 2; j++)
            ldsm4(&bf[0][2 * j][0], bTile + swoff(bRow + j * 16, bChk) * 4u);

        #pragma unroll
        for (int kk = 0; kk < 2; kk++) {
            if (kk == 0) {
                // issue k-step 1 LDSMs before the k-step 0 MMAs
                #pragma unroll
                for (int mt = 0; mt < 4; mt++)
                    ldsm4(af[1][mt], aTile + swoff(aRow + mt * 16, aChk + 2) * 4u);
                #pragma unroll
                for (int j = 0; j < 2; j++)
                    ldsm4(&bf[1][2 * j][0], bTile + swoff(bRow + j * 16, bChk + 2) * 4u);
            }
            #pragma unroll
            for (int mt = 0; mt < 4; mt++)
                #pragma unroll
                for (int nt = 0; nt < 4; nt++)
                    mma16(acc[mt][nt], af[kk][mt], bf[kk][nt]);
        }
    }

    // ---- epilogue ----
    const int rA = lane >> 2, cA = lane & 3;
    const int ldcv = ldc;

    if constexpr (EPI == 2) {
        // exp2(alpha * acc) -> bf16 P~; atomic row-sum of rounded values
        __nv_bfloat16* Cb = (__nv_bfloat16*)Cv + sC * bz;
        float* rs = res + (size_t)bz * kHW;
        #pragma unroll
        for (int mt = 0; mt < 4; mt++) {
            const int r0 = m0 + wm * 64 + mt * 16 + rA;
            float s0 = 0.f, s1 = 0.f;
            #pragma unroll
            for (int nt = 0; nt < 4; nt++) {
                const int col = n0 + wn * 32 + nt * 8 + cA * 2;
                const float e0 = exp2f(acc[mt][nt][0] * alpha);
                const float e1 = exp2f(acc[mt][nt][1] * alpha);
                const float e2 = exp2f(acc[mt][nt][2] * alpha);
                const float e3 = exp2f(acc[mt][nt][3] * alpha);
                const __nv_bfloat162 w0 = __floats2bfloat162_rn(e0, e1);
                const __nv_bfloat162 w1 = __floats2bfloat162_rn(e2, e3);
                *(__nv_bfloat162*)(Cb + (size_t)r0 * ldcv + col)       = w0;
                *(__nv_bfloat162*)(Cb + (size_t)(r0 + 8) * ldcv + col) = w1;
                s0 += __low2float(w0) + __high2float(w0);
                s1 += __low2float(w1) + __high2float(w1);
            }
            s0 += __shfl_xor_sync(0xffffffffu, s0, 1);
            s0 += __shfl_xor_sync(0xffffffffu, s0, 2);
            s1 += __shfl_xor_sync(0xffffffffu, s1, 1);
            s1 += __shfl_xor_sync(0xffffffffu, s1, 2);
            if (cA == 0) {
                atomicAdd(&rs[r0], s0);
                atomicAdd(&rs[r0 + 8], s1);
            }
        }
        return;
    }

    constexpr bool OUTB = (EPI == 0 || EPI == 1 || EPI == 5);
    #pragma unroll
    for (int mt = 0; mt < 4; mt++) {
        const int r0 = m0 + wm * 64 + mt * 16 + rA;
        float bm0 = 0.f, bm1 = 0.f;
        if (EPI == 1 || EPI == 4) { bm0 = bias[r0]; bm1 = bias[r0 + 8]; }
        if (EPI == 5) {
            bm0 = 1.f / bias[(size_t)bz * kHW + r0];
            bm1 = 1.f / bias[(size_t)bz * kHW + r0 + 8];
        }
        #pragma unroll
        for (int nt = 0; nt < 4; nt++) {
            const int col = n0 + wn * 32 + nt * 8 + cA * 2;
            float d0 = acc[mt][nt][0], d1 = acc[mt][nt][1];
            float d2 = acc[mt][nt][2], d3 = acc[mt][nt][3];
            if (EPI == 0) {
                const float b0 = bias[col], b1 = bias[col + 1];
                d0 += b0; d1 += b1; d2 += b0; d3 += b1;
            } else if (EPI == 1 || EPI == 4) {
                d0 += bm0; d1 += bm0; d2 += bm1; d3 += bm1;
            } else if (EPI == 5) {
                d0 *= bm0; d1 *= bm0; d2 *= bm1; d3 *= bm1;
            }
            if (EPI == 4) {
                const float* rp = res + sC * bz;
                d0 += rp[(size_t)r0 * ldcv + col];
                d1 += rp[(size_t)r0 * ldcv + col + 1];
                d2 += rp[(size_t)(r0 + 8) * ldcv + col];
                d3 += rp[(size_t)(r0 + 8) * ldcv + col + 1];
            }
            if (OUTB) {
                __nv_bfloat16* Cb = (__nv_bfloat16*)Cv + sC * bz;
                *(__nv_bfloat162*)(Cb + (size_t)r0 * ldcv + col) =
                    __floats2bfloat162_rn(d0, d1);
                *(__nv_bfloat162*)(Cb + (size_t)(r0 + 8) * ldcv + col) =
                    __floats2bfloat162_rn(d2, d3);
            } else {
                float* Cb = (float*)Cv + sC * bz;
                *(float2*)(Cb + (size_t)r0 * ldcv + col)       = make_float2(d0, d1);
                *(float2*)(Cb + (size_t)(r0 + 8) * ldcv + col) = make_float2(d2, d3);
            }
        }
    }
}

// ---------------------------------------------------------------------------
extern "C" void kernel_launch(void* const* d_in, const int* in_sizes, int n_in,
                              void* d_out, int out_size) {
    const float* x     = (const float*)d_in[0];
    const float* gamma = (const float*)d_in[1];
    const float* beta  = (const float*)d_in[2];
    const float* wq    = (const float*)d_in[3];
    const float* bq    = (const float*)d_in[4];
    const float* wk    = (const float*)d_in[5];
    const float* bk    = (const float*)d_in[6];
    const float* wv    = (const float*)d_in[7];
    const float* bv    = (const float*)d_in[8];
    const float* wo    = (const float*)d_in[9];
    const float* bo    = (const float*)d_in[10];
    float* out = (float*)d_out;

    __nv_bfloat16 *hT, *qkt, *v, *o2, *simh, *wh;
    float *aff, *rs, *bqk;
    cudaGetSymbolAddress((void**)&hT,   g_hT);
    cudaGetSymbolAddress((void**)&qkt,  g_qkt);
    cudaGetSymbolAddress((void**)&v,    g_v);
    cudaGetSymbolAddress((void**)&o2,   g_o2);
    cudaGetSymbolAddress((void**)&simh, g_simh);
    cudaGetSymbolAddress((void**)&aff,  g_aff);
    cudaGetSymbolAddress((void**)&rs,   g_rs);
    cudaGetSymbolAddress((void**)&wh,   g_wh);
    cudaGetSymbolAddress((void**)&bqk,  g_bqk);

    const size_t sNC = (size_t)kHW * kC;      // per-batch [n][c] / [c][n]
    const size_t sQK = (size_t)kHW * 1024;    // per-batch [n][1024]
    const size_t sNN = (size_t)kHW * kHW;     // per-batch sim
    const float  scale  = 1.0f / sqrtf((float)kC);
    const float  scale2 = scale * 1.4426950408889634f;   // fold log2(e)
    const int nW = kC * kC;

    // 0) weights -> bf16 (+ concat q/k bias); zero row sums
    prep_weights<<<(nW + 255) / 256, 256>>>(wq, wk, wv, wo, bq, bk, wh, bqk);
    rs_init<<<kB * kHW / 256, 256>>>(rs);

    // 1) GroupNorm (stats + fused normalize-transpose-bf16)
    gn_stats<<<kB * kG, 256>>>(x, gamma, beta, aff);
    gn_norm_t<<<dim3(kHW / 32, kC / 32, kB), dim3(32, 8)>>>(x, aff, hT);

    // 2) [Q|K]^T = hT @ [Wq;Wk]^T  (M=4096, N=1024, K=512), bias over columns
    {
        dim3 grid(1024 / 128, kHW / 128, kB);
        gemm_bf16<0><<<grid, 256>>>(hT, wh, bqk, nullptr, qkt,
                                    kC, kC, 1024, kC, sNC, 0, sQK, 1.f);
    }
    // 3) V = Wv @ H  (M=512, N=4096, K=512), output [c][n], bias over rows
    {
        dim3 grid(kHW / 128, kC / 128, kB);
        gemm_bf16<1><<<grid, 256>>>(wh + 2 * nW, hT, bv, nullptr, v,
                                    kC, kC, kHW, kC, 0, sNC, sNC, 1.f);
    }
    // 4) P~ = exp2(scale2 * Qt@Kt^T) -> bf16, + row sums (M=N=4096, K=512)
    {
        dim3 grid(kHW / 128, kHW / 128, kB);
        gemm_bf16<2><<<grid, 256>>>(qkt, qkt + 512, nullptr, rs, simh,
                                    1024, 1024, kHW, kC, sQK, sQK, sNN, scale2);
    }
    // 5) o2 = (P~ @ V^T) / rowsum  (M=4096, N=512, K=4096), output [n][c] bf16
    {
        dim3 grid(kC / 128, kHW / 128, kB);
        gemm_bf16<5><<<grid, 256>>>(simh, v, rs, nullptr, o2,
                                    kHW, kHW, kC, kHW, sNN, sNC, sNC, 1.f);
    }
    // 6) out = x + Wo @ o2^T + bo  (M=512, N=4096, K=512), f32 out
    {
        dim3 grid(kHW / 128, kC / 128, kB);
        gemm_bf16<4><<<grid, 256>>>(wh + 3 * nW, o2, bo, (float*)x, out,
                                    kC, kC, kHW, kC, 0, sNC, sNC, 1.f);
    }
}

// round 15
// speedup vs baseline: 1.3297x; 1.0259x over previous
#include <cuda_runtime.h>
#include <cuda_bf16.h>
#include <cstdint>
#include <math.h>

// ---------------------------------------------------------------------------
// Problem constants
// ---------------------------------------------------------------------------
constexpr int kB  = 4;
constexpr int kC  = 512;
constexpr int kHW = 4096;
constexpr int kG  = 32;
constexpr int kCPG = kC / kG;   // 16
constexpr float kEPS = 1e-6f;

// Scratch (__device__ globals per allocation-free rule)
__device__ __nv_bfloat16 g_hT  [(size_t)kB * kHW * kC];    // GN out [b][n][c]
__device__ __nv_bfloat16 g_qkt [(size_t)kB * kHW * 1024];  // [b][n][q||k]
__device__ __nv_bfloat16 g_v   [(size_t)kB * kC * kHW];    // V [b][c][n]
__device__ __nv_bfloat16 g_o2  [(size_t)kB * kHW * kC];    // attn@V [b][n][c]
__device__ __nv_bfloat16 g_simh[(size_t)kB * kHW * kHW];   // P~ bf16 (128 MB)
__device__ float         g_rs  [(size_t)kB * kHW];         // softmax row sums
__device__ float         g_aff [(size_t)kB * kC * 2];      // (scale, offset)
__device__ __nv_bfloat16 g_wh  [4 * kC * kC];              // bf16 wq,wk,wv,wo
__device__ float         g_bqk [2 * kC];                   // bq || bk

// ---------------------------------------------------------------------------
// Helpers
// ---------------------------------------------------------------------------
__device__ __forceinline__ uint32_t smem_u32(const void* p) {
    uint32_t a;
    asm("{ .reg .u64 t; cvta.to.shared.u64 t, %1; cvt.u32.u64 %0, t; }"
        : "=r"(a) : "l"(p));
    return a;
}
__device__ __forceinline__ void cp16(uint32_t dst, const void* src) {
    asm volatile("cp.async.cg.shared.global [%0], [%1], 16;\n"
                 :: "r"(dst), "l"(src));
}
__device__ __forceinline__ void cp_commit() {
    asm volatile("cp.async.commit_group;\n" ::: "memory");
}
template <int N>
__device__ __forceinline__ void cp_wait() {
    asm volatile("cp.async.wait_group %0;\n" :: "n"(N) : "memory");
}
// m16n8k16 bf16 mma, row.col, fp32 accum
__device__ __forceinline__ void mma16(float* d, const uint32_t* a, const uint32_t* b) {
    asm volatile(
        "mma.sync.aligned.m16n8k16.row.col.f32.bf16.bf16.f32 "
        "{%0,%1,%2,%3}, {%4,%5,%6,%7}, {%8,%9}, {%0,%1,%2,%3};"
        : "+f"(d[0]), "+f"(d[1]), "+f"(d[2]), "+f"(d[3])
        : "r"(a[0]), "r"(a[1]), "r"(a[2]), "r"(a[3]), "r"(b[0]), "r"(b[1]));
}
// ldmatrix 4x (m8n8 b16)
__device__ __forceinline__ void ldsm4(uint32_t* r, uint32_t addr) {
    asm volatile(
        "ldmatrix.sync.aligned.m8n8.x4.shared.b16 {%0,%1,%2,%3}, [%4];"
        : "=r"(r[0]), "=r"(r[1]), "=r"(r[2]), "=r"(r[3]) : "r"(addr));
}

// ---------------------------------------------------------------------------
// Prep: weights -> bf16 (float4), bias concat, rs zero. 256 blocks x 256 thr.
// ---------------------------------------------------------------------------
__global__ void prep_all(const float* __restrict__ wq, const float* __restrict__ wk,
                         const float* __restrict__ wv, const float* __restrict__ wo,
                         const float* __restrict__ bq, const float* __restrict__ bk,
                         __nv_bfloat16* __restrict__ wh, float* __restrict__ bqk,
                         float* __restrict__ rs) {
    const int i = blockIdx.x * blockDim.x + threadIdx.x;   // 0..65535
    const int n4 = kC * kC / 4;                            // 65536
    __nv_bfloat162* wh2 = (__nv_bfloat162*)wh;
    if (i < n4) {
        const float4 a = ((const float4*)wq)[i];
        const float4 b = ((const float4*)wk)[i];
        const float4 c = ((const float4*)wv)[i];
        const float4 d = ((const float4*)wo)[i];
        wh2[0 * n4 * 2 + 2 * i + 0] = __floats2bfloat162_rn(a.x, a.y);
        wh2[0 * n4 * 2 + 2 * i + 1] = __floats2bfloat162_rn(a.z, a.w);
        wh2[1 * n4 * 2 + 2 * i + 0] = __floats2bfloat162_rn(b.x, b.y);
        wh2[1 * n4 * 2 + 2 * i + 1] = __floats2bfloat162_rn(b.z, b.w);
        wh2[2 * n4 * 2 + 2 * i + 0] = __floats2bfloat162_rn(c.x, c.y);
        wh2[2 * n4 * 2 + 2 * i + 1] = __floats2bfloat162_rn(c.z, c.w);
        wh2[3 * n4 * 2 + 2 * i + 0] = __floats2bfloat162_rn(d.x, d.y);
        wh2[3 * n4 * 2 + 2 * i + 1] = __floats2bfloat162_rn(d.z, d.w);
    }
    if (i < kC)               bqk[i] = bq[i];
    else if (i < 2 * kC)      bqk[i] = bk[i - kC];
    if (i < kB * kHW)         rs[i] = 0.f;
}

// ---------------------------------------------------------------------------
// GroupNorm pass 1: per-(b,g) mean/var -> per-channel affine (float4 loads)
// ---------------------------------------------------------------------------
__global__ void gn_stats(const float* __restrict__ x,
                         const float* __restrict__ gamma,
                         const float* __restrict__ beta,
                         float* __restrict__ aff) {
    const int b = blockIdx.x / kG, g = blockIdx.x % kG;
    const float4* xp = (const float4*)(x + ((size_t)b * kC + (size_t)g * kCPG) * kHW);
    const int N4 = kCPG * kHW / 4;    // 16384

    float s = 0.f, ss = 0.f;
    for (int i = threadIdx.x; i < N4; i += 256) {
        const float4 v = xp[i];
        s  += v.x + v.y + v.z + v.w;
        ss += v.x * v.x + v.y * v.y + v.z * v.z + v.w * v.w;
    }
    __shared__ float sh1[256], sh2[256];
    sh1[threadIdx.x] = s; sh2[threadIdx.x] = ss;
    __syncthreads();
    for (int o = 128; o > 0; o >>= 1) {
        if (threadIdx.x < o) {
            sh1[threadIdx.x] += sh1[threadIdx.x + o];
            sh2[threadIdx.x] += sh2[threadIdx.x + o];
        }
        __syncthreads();
    }
    if (threadIdx.x < kCPG) {
        const float N = (float)(kCPG * kHW);
        const float mean = sh1[0] / N;
        const float var  = sh2[0] / N - mean * mean;
        const float rinv = rsqrtf(var + kEPS);
        const int ch = g * kCPG + threadIdx.x;
        const float a = rinv * gamma[ch];
        aff[((size_t)b * kC + ch) * 2 + 0] = a;
        aff[((size_t)b * kC + ch) * 2 + 1] = beta[ch] - mean * a;
    }
}

// ---------------------------------------------------------------------------
// GroupNorm pass 2: normalize + transpose + bf16: x[b][c][n] -> hT[b][n][c]
// Tile 128n x 32c, block (32,8). float4 loads, bf16x2 stores.
// ---------------------------------------------------------------------------
__global__ void gn_norm_t(const float* __restrict__ x,
                          const float* __restrict__ aff,
                          __nv_bfloat16* __restrict__ hT) {
    __shared__ float t[32][129];
    const int b = blockIdx.z;
    const int n0 = blockIdx.x * 128, c0 = blockIdx.y * 32;
    const int tx = threadIdx.x, ty = threadIdx.y;   // 32 x 8
    const int tid = ty * 32 + tx;
    const float* xb = x  + (size_t)b * kC * kHW;
    __nv_bfloat16* hb = hT + (size_t)b * kHW * kC;

    #pragma unroll
    for (int r = 0; r < 4; r++) {
        const int cl = ty + r * 8;                   // 0..31
        const int c = c0 + cl;
        const float a  = aff[((size_t)b * kC + c) * 2 + 0];
        const float bb = aff[((size_t)b * kC + c) * 2 + 1];
        const float4 v = *(const float4*)(xb + (size_t)c * kHW + n0 + tx * 4);
        t[cl][tx * 4 + 0] = v.x * a + bb;
        t[cl][tx * 4 + 1] = v.y * a + bb;
        t[cl][tx * 4 + 2] = v.z * a + bb;
        t[cl][tx * 4 + 3] = v.w * a + bb;
    }
    __syncthreads();
    const int c2 = (tid & 15) * 2;
    #pragma unroll
    for (int rr = 0; rr < 8; rr++) {
        const int nl = (tid >> 4) + rr * 16;         // 0..127
        *(__nv_bfloat162*)(hb + (size_t)(n0 + nl) * kC + c0 + c2) =
            __floats2bfloat162_rn(t[c2][nl], t[c2 + 1][nl]);
    }
}

// ---------------------------------------------------------------------------
// Shared GEMM constants (128x128x32 tile, 3-stage, lead 2, 2 CTAs/SM)
// ---------------------------------------------------------------------------
constexpr int kRowW   = 16;              // words per tile row (32 bf16)
constexpr int kTileW  = 128 * kRowW;     // 2048 words = 8 KB per tile
constexpr int kStageW = 2 * kTileW;      // A + B = 16 KB per stage
constexpr int kNS     = 3;               // stages (48 KB total)

__device__ __forceinline__ uint32_t swoff(int row, int c) {
    return (uint32_t)(row * kRowW + ((c ^ ((row >> 1) & 3)) << 2));
}

// ---------------------------------------------------------------------------
// Merged QK + V projection GEMM (both consume hT, K=512).
// grid (384, 1, kB): id<256 -> QK tile (nx=id%8, my=id/8), N=1024, col bias.
//                    id>=256 -> V tile (nx=(id-256)%32, my=(id-256)/32), row bias.
// ---------------------------------------------------------------------------
__global__ void __launch_bounds__(256, 2)
gemm_qkv(const __nv_bfloat16* __restrict__ hT, const __nv_bfloat16* __restrict__ wh,
         const float* __restrict__ bqk, const float* __restrict__ bv,
         __nv_bfloat16* __restrict__ qkt, __nv_bfloat16* __restrict__ vout) {
    __shared__ __align__(16) uint32_t sm[kNS * kStageW];
    const int tid = threadIdx.x;
    const int lane = tid & 31, wid = tid >> 5;
    const int wm = wid & 1, wn = wid >> 1;

    const int bz = blockIdx.z;
    const int id = blockIdx.x;
    const bool isV = (id >= 256);
    const int nx = isV ? (id - 256) % 32 : id % 8;
    const int my = isV ? (id - 256) / 32 : id / 8;
    const int m0 = my * 128;
    const int n0 = nx * 128;

    const __nv_bfloat16* hb = hT + (size_t)bz * kHW * kC;
    const __nv_bfloat16* A = isV ? wh + 2 * kC * kC : hb;   // lda = 512
    const __nv_bfloat16* B = isV ? hb : wh;                  // ldb = 512

    const uint32_t smAddr = smem_u32(sm);
    constexpr int KT = kC / 32;    // 16

    const int lg   = lane >> 3;
    const int lrow = lane & 7;
    const int aRow = wm * 64 + (lg & 1) * 8 + lrow;
    const int aChk = lg >> 1;
    const int bRow = wn * 32 + (lg >> 1) * 8 + lrow;
    const int bChk = lg & 1;

    const int pr0 = tid >> 2, pc0 = tid & 3;
    const int pr1 = (256 + tid) >> 2, pc1 = (256 + tid) & 3;
    const uint32_t pOff0 = swoff(pr0, pc0) * 4u;
    const uint32_t pOff1 = swoff(pr1, pc1) * 4u;
    const __nv_bfloat16* gA0 = A + (size_t)(m0 + pr0) * kC + pc0 * 8;
    const __nv_bfloat16* gA1 = A + (size_t)(m0 + pr1) * kC + pc1 * 8;
    const __nv_bfloat16* gB0 = B + (size_t)(n0 + pr0) * kC + pc0 * 8;
    const __nv_bfloat16* gB1 = B + (size_t)(n0 + pr1) * kC + pc1 * 8;

    auto prefetch = [&](int it, int s) {
        const int k0 = it * 32;
        const uint32_t aBase = smAddr + (uint32_t)(s * kStageW) * 4u;
        const uint32_t bBase = aBase + (uint32_t)kTileW * 4u;
        cp16(aBase + pOff0, gA0 + k0);
        cp16(aBase + pOff1, gA1 + k0);
        cp16(bBase + pOff0, gB0 + k0);
        cp16(bBase + pOff1, gB1 + k0);
    };

    float acc[4][4][4];
    #pragma unroll
    for (int i = 0; i < 4; i++)
        #pragma unroll
        for (int j = 0; j < 4; j++)
            #pragma unroll
            for (int r = 0; r < 4; r++) acc[i][j][r] = 0.f;

    prefetch(0, 0); cp_commit();
    prefetch(1, 1); cp_commit();

    uint32_t af[2][4][4];
    uint32_t bf[2][4][2];

    for (int it = 0; it < KT; ++it) {
        cp_wait<1>();
        __syncthreads();
        if (it + 2 < KT) prefetch(it + 2, (it + 2) % kNS);
        cp_commit();

        const uint32_t aTile = smAddr + (uint32_t)((it % kNS) * kStageW) * 4u;
        const uint32_t bTile = aTile + (uint32_t)kTileW * 4u;

        #pragma unroll
        for (int mt = 0; mt < 4; mt++)
            ldsm4(af[0][mt], aTile + swoff(aRow + mt * 16, aChk) * 4u);
        #pragma unroll
        for (int j = 0; j < 2; j++)
            ldsm4(&bf[0][2 * j][0], bTile + swoff(bRow + j * 16, bChk) * 4u);

        #pragma unroll
        for (int kk = 0; kk < 2; kk++) {
            if (kk == 0) {
                #pragma unroll
                for (int mt = 0; mt < 4; mt++)
                    ldsm4(af[1][mt], aTile + swoff(aRow + mt * 16, aChk + 2) * 4u);
                #pragma unroll
                for (int j = 0; j < 2; j++)
                    ldsm4(&bf[1][2 * j][0], bTile + swoff(bRow + j * 16, bChk + 2) * 4u);
            }
            #pragma unroll
            for (int mt = 0; mt < 4; mt++)
                #pragma unroll
                for (int nt = 0; nt < 4; nt++)
                    mma16(acc[mt][nt], af[kk][mt], bf[kk][nt]);
        }
    }

    // epilogue
    const int rA = lane >> 2, cA = lane & 3;
    const int ldc = isV ? kHW : 1024;
    __nv_bfloat16* Cb = isV ? vout + (size_t)bz * kC * kHW
                            : qkt + (size_t)bz * kHW * 1024;
    #pragma unroll
    for (int mt = 0; mt < 4; mt++) {
        const int r0 = m0 + wm * 64 + mt * 16 + rA;
        float bm0 = 0.f, bm1 = 0.f;
        if (isV) { bm0 = bv[r0]; bm1 = bv[r0 + 8]; }
        #pragma unroll
        for (int nt = 0; nt < 4; nt++) {
            const int col = n0 + wn * 32 + nt * 8 + cA * 2;
            float d0 = acc[mt][nt][0], d1 = acc[mt][nt][1];
            float d2 = acc[mt][nt][2], d3 = acc[mt][nt][3];
            if (isV) {
                d0 += bm0; d1 += bm0; d2 += bm1; d3 += bm1;
            } else {
                const float b0 = bqk[col], b1 = bqk[col + 1];
                d0 += b0; d1 += b1; d2 += b0; d3 += b1;
            }
            *(__nv_bfloat162*)(Cb + (size_t)r0 * ldc + col) =
                __floats2bfloat162_rn(d0, d1);
            *(__nv_bfloat162*)(Cb + (size_t)(r0 + 8) * ldc + col) =
                __floats2bfloat162_rn(d2, d3);
        }
    }
}

// ---------------------------------------------------------------------------
// General GEMM (verified Round-13 mainloop).
// EPI: 2=exp2(alpha*acc)->bf16 + atomic row-sum (softmax numerator),
//      4=+bias[m]+res[m][n]->f32, 5=acc/rowsum[m]->bf16
// ---------------------------------------------------------------------------
template <int EPI>
__global__ void __launch_bounds__(256, 2)
gemm_bf16(const __nv_bfloat16* __restrict__ A, const __nv_bfloat16* __restrict__ B,
          const float* __restrict__ bias, float* __restrict__ res,
          void* __restrict__ Cv,
          int lda, int ldb, int ldc, int K,
          size_t sA, size_t sB, size_t sC, float alpha) {
    __shared__ __align__(16) uint32_t sm[kNS * kStageW];
    const int tid = threadIdx.x;
    const int lane = tid & 31, wid = tid >> 5;
    const int wm = wid & 1, wn = wid >> 1;

    const int bz = blockIdx.z;
    const int m0 = blockIdx.y * 128;
    const int n0 = blockIdx.x * 128;

    const uint32_t smAddr = smem_u32(sm);
    const int KT = K / 32;

    const int lg   = lane >> 3;
    const int lrow = lane & 7;
    const int aRow = wm * 64 + (lg & 1) * 8 + lrow;
    const int aChk = lg >> 1;
    const int bRow = wn * 32 + (lg >> 1) * 8 + lrow;
    const int bChk = lg & 1;

    const int pr0 = tid >> 2, pc0 = tid & 3;
    const int pr1 = (256 + tid) >> 2, pc1 = (256 + tid) & 3;
    const uint32_t pOff0 = swoff(pr0, pc0) * 4u;
    const uint32_t pOff1 = swoff(pr1, pc1) * 4u;
    const __nv_bfloat16* gA0 = A + sA * bz + (size_t)(m0 + pr0) * lda + pc0 * 8;
    const __nv_bfloat16* gA1 = A + sA * bz + (size_t)(m0 + pr1) * lda + pc1 * 8;
    const __nv_bfloat16* gB0 = B + sB * bz + (size_t)(n0 + pr0) * ldb + pc0 * 8;
    const __nv_bfloat16* gB1 = B + sB * bz + (size_t)(n0 + pr1) * ldb + pc1 * 8;

    auto prefetch = [&](int it, int s) {
        const int k0 = it * 32;
        const uint32_t aBase = smAddr + (uint32_t)(s * kStageW) * 4u;
        const uint32_t bBase = aBase + (uint32_t)kTileW * 4u;
        cp16(aBase + pOff0, gA0 + k0);
        cp16(aBase + pOff1, gA1 + k0);
        cp16(bBase + pOff0, gB0 + k0);
        cp16(bBase + pOff1, gB1 + k0);
    };

    float acc[4][4][4];
    #pragma unroll
    for (int i = 0; i < 4; i++)
        #pragma unroll
        for (int j = 0; j < 4; j++)
            #pragma unroll
            for (int r = 0; r < 4; r++) acc[i][j][r] = 0.f;

    prefetch(0, 0); cp_commit();
    prefetch(1, 1); cp_commit();

    uint32_t af[2][4][4];
    uint32_t bf[2][4][2];

    for (int it = 0; it < KT; ++it) {
        cp_wait<1>();
        __syncthreads();
        if (it + 2 < KT) prefetch(it + 2, (it + 2) % kNS);
        cp_commit();

        const uint32_t aTile = smAddr + (uint32_t)((it % kNS) * kStageW) * 4u;
        const uint32_t bTile = aTile + (uint32_t)kTileW * 4u;

        #pragma unroll
        for (int mt = 0; mt < 4; mt++)
            ldsm4(af[0][mt], aTile + swoff(aRow + mt * 16, aChk) * 4u);
        #pragma unroll
        for (int j = 0; j < 2; j++)
            ldsm4(&bf[0][2 * j][0], bTile + swoff(bRow + j * 16, bChk) * 4u);

        #pragma unroll
        for (int kk = 0; kk < 2; kk++) {
            if (kk == 0) {
                #pragma unroll
                for (int mt = 0; mt < 4; mt++)
                    ldsm4(af[1][mt], aTile + swoff(aRow + mt * 16, aChk + 2) * 4u);
                #pragma unroll
                for (int j = 0; j < 2; j++)
                    ldsm4(&bf[1][2 * j][0], bTile + swoff(bRow + j * 16, bChk + 2) * 4u);
            }
            #pragma unroll
            for (int mt = 0; mt < 4; mt++)
                #pragma unroll
                for (int nt = 0; nt < 4; nt++)
                    mma16(acc[mt][nt], af[kk][mt], bf[kk][nt]);
        }
    }

    // ---- epilogue ----
    const int rA = lane >> 2, cA = lane & 3;

    if constexpr (EPI == 2) {
        __nv_bfloat16* Cb = (__nv_bfloat16*)Cv + sC * bz;
        float* rs = res + (size_t)bz * kHW;
        #pragma unroll
        for (int mt = 0; mt < 4; mt++) {
            const int r0 = m0 + wm * 64 + mt * 16 + rA;
            float s0 = 0.f, s1 = 0.f;
            #pragma unroll
            for (int nt = 0; nt < 4; nt++) {
                const int col = n0 + wn * 32 + nt * 8 + cA * 2;
                const float e0 = exp2f(acc[mt][nt][0] * alpha);
                const float e1 = exp2f(acc[mt][nt][1] * alpha);
                const float e2 = exp2f(acc[mt][nt][2] * alpha);
                const float e3 = exp2f(acc[mt][nt][3] * alpha);
                const __nv_bfloat162 w0 = __floats2bfloat162_rn(e0, e1);
                const __nv_bfloat162 w1 = __floats2bfloat162_rn(e2, e3);
                *(__nv_bfloat162*)(Cb + (size_t)r0 * ldc + col)       = w0;
                *(__nv_bfloat162*)(Cb + (size_t)(r0 + 8) * ldc + col) = w1;
                s0 += __low2float(w0) + __high2float(w0);
                s1 += __low2float(w1) + __high2float(w1);
            }
            s0 += __shfl_xor_sync(0xffffffffu, s0, 1);
            s0 += __shfl_xor_sync(0xffffffffu, s0, 2);
            s1 += __shfl_xor_sync(0xffffffffu, s1, 1);
            s1 += __shfl_xor_sync(0xffffffffu, s1, 2);
            if (cA == 0) {
                atomicAdd(&rs[r0], s0);
                atomicAdd(&rs[r0 + 8], s1);
            }
        }
        return;
    }

    #pragma unroll
    for (int mt = 0; mt < 4; mt++) {
        const int r0 = m0 + wm * 64 + mt * 16 + rA;
        float bm0 = 0.f, bm1 = 0.f;
        if (EPI == 4) { bm0 = bias[r0]; bm1 = bias[r0 + 8]; }
        if (EPI == 5) {
            bm0 = 1.f / bias[(size_t)bz * kHW + r0];
            bm1 = 1.f / bias[(size_t)bz * kHW + r0 + 8];
        }
        #pragma unroll
        for (int nt = 0; nt < 4; nt++) {
            const int col = n0 + wn * 32 + nt * 8 + cA * 2;
            float d0 = acc[mt][nt][0], d1 = acc[mt][nt][1];
            float d2 = acc[mt][nt][2], d3 = acc[mt][nt][3];
            if (EPI == 4) {
                d0 += bm0; d1 += bm0; d2 += bm1; d3 += bm1;
            } else if (EPI == 5) {
                d0 *= bm0; d1 *= bm0; d2 *= bm1; d3 *= bm1;
            }
            if (EPI == 4) {
                const float* rp = res + sC * bz;
                d0 += rp[(size_t)r0 * ldc + col];
                d1 += rp[(size_t)r0 * ldc + col + 1];
                d2 += rp[(size_t)(r0 + 8) * ldc + col];
                d3 += rp[(size_t)(r0 + 8) * ldc + col + 1];
                float* Cb = (float*)Cv + sC * bz;
                *(float2*)(Cb + (size_t)r0 * ldc + col)       = make_float2(d0, d1);
                *(float2*)(Cb + (size_t)(r0 + 8) * ldc + col) = make_float2(d2, d3);
            } else {
                __nv_bfloat16* Cb = (__nv_bfloat16*)Cv + sC * bz;
                *(__nv_bfloat162*)(Cb + (size_t)r0 * ldc + col) =
                    __floats2bfloat162_rn(d0, d1);
                *(__nv_bfloat162*)(Cb + (size_t)(r0 + 8) * ldc + col) =
                    __floats2bfloat162_rn(d2, d3);
            }
        }
    }
}

// ---------------------------------------------------------------------------
extern "C" void kernel_launch(void* const* d_in, const int* in_sizes, int n_in,
                              void* d_out, int out_size) {
    const float* x     = (const float*)d_in[0];
    const float* gamma = (const float*)d_in[1];
    const float* beta  = (const float*)d_in[2];
    const float* wq    = (const float*)d_in[3];
    const float* bq    = (const float*)d_in[4];
    const float* wk    = (const float*)d_in[5];
    const float* bk    = (const float*)d_in[6];
    const float* wv    = (const float*)d_in[7];
    const float* bv    = (const float*)d_in[8];
    const float* wo    = (const float*)d_in[9];
    const float* bo    = (const float*)d_in[10];
    float* out = (float*)d_out;

    __nv_bfloat16 *hT, *qkt, *v, *o2, *simh, *wh;
    float *aff, *rs, *bqk;
    cudaGetSymbolAddress((void**)&hT,   g_hT);
    cudaGetSymbolAddress((void**)&qkt,  g_qkt);
    cudaGetSymbolAddress((void**)&v,    g_v);
    cudaGetSymbolAddress((void**)&o2,   g_o2);
    cudaGetSymbolAddress((void**)&simh, g_simh);
    cudaGetSymbolAddress((void**)&aff,  g_aff);
    cudaGetSymbolAddress((void**)&rs,   g_rs);
    cudaGetSymbolAddress((void**)&wh,   g_wh);
    cudaGetSymbolAddress((void**)&bqk,  g_bqk);

    const size_t sNC = (size_t)kHW * kC;
    const size_t sQK = (size_t)kHW * 1024;
    const size_t sNN = (size_t)kHW * kHW;
    const float  scale  = 1.0f / sqrtf((float)kC);
    const float  scale2 = scale * 1.4426950408889634f;
    const int nW = kC * kC;

    // 0) prep: weights->bf16, bias concat, rs zero
    prep_all<<<256, 256>>>(wq, wk, wv, wo, bq, bk, wh, bqk, rs);

    // 1) GroupNorm
    gn_stats<<<kB * kG, 256>>>(x, gamma, beta, aff);
    gn_norm_t<<<dim3(kHW / 128, kC / 32, kB), dim3(32, 8)>>>(x, aff, hT);

    // 2) merged QK + V projections (one launch, 384 CTAs per batch)
    gemm_qkv<<<dim3(384, 1, kB), 256>>>(hT, wh, bqk, bv, qkt, v);

    // 3) P~ = exp2(scale2 * Qt@Kt^T) -> bf16, + row sums (M=N=4096, K=512)
    {
        dim3 grid(kHW / 128, kHW / 128, kB);
        gemm_bf16<2><<<grid, 256>>>(qkt, qkt + 512, nullptr, rs, simh,
                                    1024, 1024, kHW, kC, sQK, sQK, sNN, scale2);
    }
    // 4) o2 = (P~ @ V^T) / rowsum  (M=4096, N=512, K=4096), output [n][c] bf16
    {
        dim3 grid(kC / 128, kHW / 128, kB);
        gemm_bf16<5><<<grid, 256>>>(simh, v, rs, nullptr, o2,
                                    kHW, kHW, kC, kHW, sNN, sNC, sNC, 1.f);
    }
    // 5) out = x + Wo @ o2^T + bo  (M=512, N=4096, K=512), f32 out
    {
        dim3 grid(kHW / 128, kC / 128, kB);
        gemm_bf16<4><<<grid, 256>>>(wh + 3 * nW, o2, bo, (float*)x, out,
                                    kC, kC, kHW, kC, 0, sNC, sNC, 1.f);
    }
}

// round 16
// speedup vs baseline: 1.3612x; 1.0236x over previous
#include <cuda_runtime.h>
#include <cuda_bf16.h>
#include <cstdint>
#include <math.h>

// ---------------------------------------------------------------------------
// Problem constants
// ---------------------------------------------------------------------------
constexpr int kB  = 4;
constexpr int kC  = 512;
constexpr int kHW = 4096;
constexpr int kG  = 32;
constexpr int kCPG = kC / kG;   // 16
constexpr float kEPS = 1e-6f;

// Scratch (__device__ globals per allocation-free rule)
__device__ __nv_bfloat16 g_hT  [(size_t)kB * kHW * kC];    // GN out [b][n][c]
__device__ __nv_bfloat16 g_qkt [(size_t)kB * kHW * 1024];  // [b][n][q||k]
__device__ __nv_bfloat16 g_v   [(size_t)kB * kC * kHW];    // V [b][c][n]
__device__ __nv_bfloat16 g_o2  [(size_t)kB * kHW * kC];    // attn@V [b][n][c]
__device__ __nv_bfloat16 g_simh[(size_t)kB * kHW * kHW];   // P~ bf16 (128 MB)
__device__ float         g_rs  [(size_t)kB * kHW];         // softmax row sums
__device__ float         g_aff [(size_t)kB * kC * 2];      // (scale, offset)
__device__ __nv_bfloat16 g_wh  [4 * kC * kC];              // bf16 wq,wk,wv,wo
__device__ float         g_bqk [2 * kC];                   // bq || bk

// ---------------------------------------------------------------------------
// Helpers
// ---------------------------------------------------------------------------
__device__ __forceinline__ uint32_t smem_u32(const void* p) {
    uint32_t a;
    asm("{ .reg .u64 t; cvta.to.shared.u64 t, %1; cvt.u32.u64 %0, t; }"
        : "=r"(a) : "l"(p));
    return a;
}
__device__ __forceinline__ void cp16(uint32_t dst, const void* src) {
    asm volatile("cp.async.cg.shared.global [%0], [%1], 16;\n"
                 :: "r"(dst), "l"(src));
}
__device__ __forceinline__ void cp_commit() {
    asm volatile("cp.async.commit_group;\n" ::: "memory");
}
template <int N>
__device__ __forceinline__ void cp_wait() {
    asm volatile("cp.async.wait_group %0;\n" :: "n"(N) : "memory");
}
// single-instruction exp2 (MUFU.EX2)
__device__ __forceinline__ float ex2(float x) {
    float y;
    asm("ex2.approx.ftz.f32 %0, %1;" : "=f"(y) : "f"(x));
    return y;
}
// m16n8k16 bf16 mma, row.col, fp32 accum
__device__ __forceinline__ void mma16(float* d, const uint32_t* a, const uint32_t* b) {
    asm volatile(
        "mma.sync.aligned.m16n8k16.row.col.f32.bf16.bf16.f32 "
        "{%0,%1,%2,%3}, {%4,%5,%6,%7}, {%8,%9}, {%0,%1,%2,%3};"
        : "+f"(d[0]), "+f"(d[1]), "+f"(d[2]), "+f"(d[3])
        : "r"(a[0]), "r"(a[1]), "r"(a[2]), "r"(a[3]), "r"(b[0]), "r"(b[1]));
}
// ldmatrix 4x (m8n8 b16)
__device__ __forceinline__ void ldsm4(uint32_t* r, uint32_t addr) {
    asm volatile(
        "ldmatrix.sync.aligned.m8n8.x4.shared.b16 {%0,%1,%2,%3}, [%4];"
        : "=r"(r[0]), "=r"(r[1]), "=r"(r[2]), "=r"(r[3]) : "r"(addr));
}

// ---------------------------------------------------------------------------
// Prep: weights -> bf16 (float4), bias concat, rs zero. 256 blocks x 256 thr.
// ---------------------------------------------------------------------------
__global__ void prep_all(const float* __restrict__ wq, const float* __restrict__ wk,
                         const float* __restrict__ wv, const float* __restrict__ wo,
                         const float* __restrict__ bq, const float* __restrict__ bk,
                         __nv_bfloat16* __restrict__ wh, float* __restrict__ bqk,
                         float* __restrict__ rs) {
    const int i = blockIdx.x * blockDim.x + threadIdx.x;   // 0..65535
    const int n4 = kC * kC / 4;                            // 65536
    __nv_bfloat162* wh2 = (__nv_bfloat162*)wh;
    if (i < n4) {
        const float4 a = ((const float4*)wq)[i];
        const float4 b = ((const float4*)wk)[i];
        const float4 c = ((const float4*)wv)[i];
        const float4 d = ((const float4*)wo)[i];
        wh2[0 * n4 * 2 + 2 * i + 0] = __floats2bfloat162_rn(a.x, a.y);
        wh2[0 * n4 * 2 + 2 * i + 1] = __floats2bfloat162_rn(a.z, a.w);
        wh2[1 * n4 * 2 + 2 * i + 0] = __floats2bfloat162_rn(b.x, b.y);
        wh2[1 * n4 * 2 + 2 * i + 1] = __floats2bfloat162_rn(b.z, b.w);
        wh2[2 * n4 * 2 + 2 * i + 0] = __floats2bfloat162_rn(c.x, c.y);
        wh2[2 * n4 * 2 + 2 * i + 1] = __floats2bfloat162_rn(c.z, c.w);
        wh2[3 * n4 * 2 + 2 * i + 0] = __floats2bfloat162_rn(d.x, d.y);
        wh2[3 * n4 * 2 + 2 * i + 1] = __floats2bfloat162_rn(d.z, d.w);
    }
    if (i < kC)               bqk[i] = bq[i];
    else if (i < 2 * kC)      bqk[i] = bk[i - kC];
    if (i < kB * kHW)         rs[i] = 0.f;
}

// ---------------------------------------------------------------------------
// GroupNorm pass 1: per-(b,g) mean/var -> per-channel affine (float4, 512 thr)
// ---------------------------------------------------------------------------
__global__ void gn_stats(const float* __restrict__ x,
                         const float* __restrict__ gamma,
                         const float* __restrict__ beta,
                         float* __restrict__ aff) {
    const int b = blockIdx.x / kG, g = blockIdx.x % kG;
    const float4* xp = (const float4*)(x + ((size_t)b * kC + (size_t)g * kCPG) * kHW);
    const int N4 = kCPG * kHW / 4;    // 16384

    float s = 0.f, ss = 0.f;
    for (int i = threadIdx.x; i < N4; i += 512) {
        const float4 v = xp[i];
        s  += v.x + v.y + v.z + v.w;
        ss += v.x * v.x + v.y * v.y + v.z * v.z + v.w * v.w;
    }
    __shared__ float sh1[512], sh2[512];
    sh1[threadIdx.x] = s; sh2[threadIdx.x] = ss;
    __syncthreads();
    for (int o = 256; o > 0; o >>= 1) {
        if (threadIdx.x < o) {
            sh1[threadIdx.x] += sh1[threadIdx.x + o];
            sh2[threadIdx.x] += sh2[threadIdx.x + o];
        }
        __syncthreads();
    }
    if (threadIdx.x < kCPG) {
        const float N = (float)(kCPG * kHW);
        const float mean = sh1[0] / N;
        const float var  = sh2[0] / N - mean * mean;
        const float rinv = rsqrtf(var + kEPS);
        const int ch = g * kCPG + threadIdx.x;
        const float a = rinv * gamma[ch];
        aff[((size_t)b * kC + ch) * 2 + 0] = a;
        aff[((size_t)b * kC + ch) * 2 + 1] = beta[ch] - mean * a;
    }
}

// ---------------------------------------------------------------------------
// GroupNorm pass 2: normalize + transpose + bf16: x[b][c][n] -> hT[b][n][c]
// Tile 128n x 32c, block (32,8). float4 loads, bf16x2 stores.
// ---------------------------------------------------------------------------
__global__ void gn_norm_t(const float* __restrict__ x,
                          const float* __restrict__ aff,
                          __nv_bfloat16* __restrict__ hT) {
    __shared__ float t[32][129];
    const int b = blockIdx.z;
    const int n0 = blockIdx.x * 128, c0 = blockIdx.y * 32;
    const int tx = threadIdx.x, ty = threadIdx.y;   // 32 x 8
    const int tid = ty * 32 + tx;
    const float* xb = x  + (size_t)b * kC * kHW;
    __nv_bfloat16* hb = hT + (size_t)b * kHW * kC;

    #pragma unroll
    for (int r = 0; r < 4; r++) {
        const int cl = ty + r * 8;                   // 0..31
        const int c = c0 + cl;
        const float a  = aff[((size_t)b * kC + c) * 2 + 0];
        const float bb = aff[((size_t)b * kC + c) * 2 + 1];
        const float4 v = *(const float4*)(xb + (size_t)c * kHW + n0 + tx * 4);
        t[cl][tx * 4 + 0] = v.x * a + bb;
        t[cl][tx * 4 + 1] = v.y * a + bb;
        t[cl][tx * 4 + 2] = v.z * a + bb;
        t[cl][tx * 4 + 3] = v.w * a + bb;
    }
    __syncthreads();
    const int c2 = (tid & 15) * 2;
    #pragma unroll
    for (int rr = 0; rr < 8; rr++) {
        const int nl = (tid >> 4) + rr * 16;         // 0..127
        *(__nv_bfloat162*)(hb + (size_t)(n0 + nl) * kC + c0 + c2) =
            __floats2bfloat162_rn(t[c2][nl], t[c2 + 1][nl]);
    }
}

// ---------------------------------------------------------------------------
// Shared GEMM constants (128x128x32 tile, 3-stage, lead 2, 2 CTAs/SM)
// ---------------------------------------------------------------------------
constexpr int kRowW   = 16;              // words per tile row (32 bf16)
constexpr int kTileW  = 128 * kRowW;     // 2048 words = 8 KB per tile
constexpr int kStageW = 2 * kTileW;      // A + B = 16 KB per stage
constexpr int kNS     = 3;               // stages (48 KB total)

__device__ __forceinline__ uint32_t swoff(int row, int c) {
    return (uint32_t)(row * kRowW + ((c ^ ((row >> 1) & 3)) << 2));
}

// ---------------------------------------------------------------------------
// Merged QK + V projection GEMM (both consume hT, K=512).
// grid (384, 1, kB): id<256 -> QK tile (nx=id%8, my=id/8), N=1024, col bias.
//                    id>=256 -> V tile (nx=(id-256)%32, my=(id-256)/32), row bias.
// ---------------------------------------------------------------------------
__global__ void __launch_bounds__(256, 2)
gemm_qkv(const __nv_bfloat16* __restrict__ hT, const __nv_bfloat16* __restrict__ wh,
         const float* __restrict__ bqk, const float* __restrict__ bv,
         __nv_bfloat16* __restrict__ qkt, __nv_bfloat16* __restrict__ vout) {
    __shared__ __align__(16) uint32_t sm[kNS * kStageW];
    const int tid = threadIdx.x;
    const int lane = tid & 31, wid = tid >> 5;
    const int wm = wid & 1, wn = wid >> 1;

    const int bz = blockIdx.z;
    const int id = blockIdx.x;
    const bool isV = (id >= 256);
    const int nx = isV ? (id - 256) % 32 : id % 8;
    const int my = isV ? (id - 256) / 32 : id / 8;
    const int m0 = my * 128;
    const int n0 = nx * 128;

    const __nv_bfloat16* hb = hT + (size_t)bz * kHW * kC;
    const __nv_bfloat16* A = isV ? wh + 2 * kC * kC : hb;   // lda = 512
    const __nv_bfloat16* B = isV ? hb : wh;                  // ldb = 512

    const uint32_t smAddr = smem_u32(sm);
    constexpr int KT = kC / 32;    // 16

    const int lg   = lane >> 3;
    const int lrow = lane & 7;
    const int aRow = wm * 64 + (lg & 1) * 8 + lrow;
    const int aChk = lg >> 1;
    const int bRow = wn * 32 + (lg >> 1) * 8 + lrow;
    const int bChk = lg & 1;

    const int pr0 = tid >> 2, pc0 = tid & 3;
    const int pr1 = (256 + tid) >> 2, pc1 = (256 + tid) & 3;
    const uint32_t pOff0 = swoff(pr0, pc0) * 4u;
    const uint32_t pOff1 = swoff(pr1, pc1) * 4u;
    const __nv_bfloat16* gA0 = A + (size_t)(m0 + pr0) * kC + pc0 * 8;
    const __nv_bfloat16* gA1 = A + (size_t)(m0 + pr1) * kC + pc1 * 8;
    const __nv_bfloat16* gB0 = B + (size_t)(n0 + pr0) * kC + pc0 * 8;
    const __nv_bfloat16* gB1 = B + (size_t)(n0 + pr1) * kC + pc1 * 8;

    auto prefetch = [&](int it, int s) {
        const int k0 = it * 32;
        const uint32_t aBase = smAddr + (uint32_t)(s * kStageW) * 4u;
        const uint32_t bBase = aBase + (uint32_t)kTileW * 4u;
        cp16(aBase + pOff0, gA0 + k0);
        cp16(aBase + pOff1, gA1 + k0);
        cp16(bBase + pOff0, gB0 + k0);
        cp16(bBase + pOff1, gB1 + k0);
    };

    float acc[4][4][4];
    #pragma unroll
    for (int i = 0; i < 4; i++)
        #pragma unroll
        for (int j = 0; j < 4; j++)
            #pragma unroll
            for (int r = 0; r < 4; r++) acc[i][j][r] = 0.f;

    prefetch(0, 0); cp_commit();
    prefetch(1, 1); cp_commit();

    uint32_t af[2][4][4];
    uint32_t bf[2][4][2];

    for (int it = 0; it < KT; ++it) {
        cp_wait<1>();
        __syncthreads();
        if (it + 2 < KT) prefetch(it + 2, (it + 2) % kNS);
        cp_commit();

        const uint32_t aTile = smAddr + (uint32_t)((it % kNS) * kStageW) * 4u;
        const uint32_t bTile = aTile + (uint32_t)kTileW * 4u;

        #pragma unroll
        for (int mt = 0; mt < 4; mt++)
            ldsm4(af[0][mt], aTile + swoff(aRow + mt * 16, aChk) * 4u);
        #pragma unroll
        for (int j = 0; j < 2; j++)
            ldsm4(&bf[0][2 * j][0], bTile + swoff(bRow + j * 16, bChk) * 4u);

        #pragma unroll
        for (int kk = 0; kk < 2; kk++) {
            if (kk == 0) {
                #pragma unroll
                for (int mt = 0; mt < 4; mt++)
                    ldsm4(af[1][mt], aTile + swoff(aRow + mt * 16, aChk + 2) * 4u);
                #pragma unroll
                for (int j = 0; j < 2; j++)
                    ldsm4(&bf[1][2 * j][0], bTile + swoff(bRow + j * 16, bChk + 2) * 4u);
            }
            #pragma unroll
            for (int mt = 0; mt < 4; mt++)
                #pragma unroll
                for (int nt = 0; nt < 4; nt++)
                    mma16(acc[mt][nt], af[kk][mt], bf[kk][nt]);
        }
    }

    // epilogue
    const int rA = lane >> 2, cA = lane & 3;
    const int ldc = isV ? kHW : 1024;
    __nv_bfloat16* Cb = isV ? vout + (size_t)bz * kC * kHW
                            : qkt + (size_t)bz * kHW * 1024;
    #pragma unroll
    for (int mt = 0; mt < 4; mt++) {
        const int r0 = m0 + wm * 64 + mt * 16 + rA;
        float bm0 = 0.f, bm1 = 0.f;
        if (isV) { bm0 = bv[r0]; bm1 = bv[r0 + 8]; }
        #pragma unroll
        for (int nt = 0; nt < 4; nt++) {
            const int col = n0 + wn * 32 + nt * 8 + cA * 2;
            float d0 = acc[mt][nt][0], d1 = acc[mt][nt][1];
            float d2 = acc[mt][nt][2], d3 = acc[mt][nt][3];
            if (isV) {
                d0 += bm0; d1 += bm0; d2 += bm1; d3 += bm1;
            } else {
                const float b0 = bqk[col], b1 = bqk[col + 1];
                d0 += b0; d1 += b1; d2 += b0; d3 += b1;
            }
            *(__nv_bfloat162*)(Cb + (size_t)r0 * ldc + col) =
                __floats2bfloat162_rn(d0, d1);
            *(__nv_bfloat162*)(Cb + (size_t)(r0 + 8) * ldc + col) =
                __floats2bfloat162_rn(d2, d3);
        }
    }
}

// ---------------------------------------------------------------------------
// General GEMM (verified Round-13 mainloop).
// EPI: 2=ex2(alpha*acc)->bf16 + atomic row-sum (softmax numerator),
//      4=+bias[m]+res[m][n]->f32, 5=acc/rowsum[m]->bf16
// ---------------------------------------------------------------------------
template <int EPI>
__global__ void __launch_bounds__(256, 2)
gemm_bf16(const __nv_bfloat16* __restrict__ A, const __nv_bfloat16* __restrict__ B,
          const float* __restrict__ bias, float* __restrict__ res,
          void* __restrict__ Cv,
          int lda, int ldb, int ldc, int K,
          size_t sA, size_t sB, size_t sC, float alpha) {
    __shared__ __align__(16) uint32_t sm[kNS * kStageW];
    const int tid = threadIdx.x;
    const int lane = tid & 31, wid = tid >> 5;
    const int wm = wid & 1, wn = wid >> 1;

    const int bz = blockIdx.z;
    const int m0 = blockIdx.y * 128;
    const int n0 = blockIdx.x * 128;

    const uint32_t smAddr = smem_u32(sm);
    const int KT = K / 32;

    const int lg   = lane >> 3;
    const int lrow = lane & 7;
    const int aRow = wm * 64 + (lg & 1) * 8 + lrow;
    const int aChk = lg >> 1;
    const int bRow = wn * 32 + (lg >> 1) * 8 + lrow;
    const int bChk = lg & 1;

    const int pr0 = tid >> 2, pc0 = tid & 3;
    const int pr1 = (256 + tid) >> 2, pc1 = (256 + tid) & 3;
    const uint32_t pOff0 = swoff(pr0, pc0) * 4u;
    const uint32_t pOff1 = swoff(pr1, pc1) * 4u;
    const __nv_bfloat16* gA0 = A + sA * bz + (size_t)(m0 + pr0) * lda + pc0 * 8;
    const __nv_bfloat16* gA1 = A + sA * bz + (size_t)(m0 + pr1) * lda + pc1 * 8;
    const __nv_bfloat16* gB0 = B + sB * bz + (size_t)(n0 + pr0) * ldb + pc0 * 8;
    const __nv_bfloat16* gB1 = B + sB * bz + (size_t)(n0 + pr1) * ldb + pc1 * 8;

    auto prefetch = [&](int it, int s) {
        const int k0 = it * 32;
        const uint32_t aBase = smAddr + (uint32_t)(s * kStageW) * 4u;
        const uint32_t bBase = aBase + (uint32_t)kTileW * 4u;
        cp16(aBase + pOff0, gA0 + k0);
        cp16(aBase + pOff1, gA1 + k0);
        cp16(bBase + pOff0, gB0 + k0);
        cp16(bBase + pOff1, gB1 + k0);
    };

    float acc[4][4][4];
    #pragma unroll
    for (int i = 0; i < 4; i++)
        #pragma unroll
        for (int j = 0; j < 4; j++)
            #pragma unroll
            for (int r = 0; r < 4; r++) acc[i][j][r] = 0.f;

    prefetch(0, 0); cp_commit();
    prefetch(1, 1); cp_commit();

    uint32_t af[2][4][4];
    uint32_t bf[2][4][2];

    for (int it = 0; it < KT; ++it) {
        cp_wait<1>();
        __syncthreads();
        if (it + 2 < KT) prefetch(it + 2, (it + 2) % kNS);
        cp_commit();

        const uint32_t aTile = smAddr + (uint32_t)((it % kNS) * kStageW) * 4u;
        const uint32_t bTile = aTile + (uint32_t)kTileW * 4u;

        #pragma unroll
        for (int mt = 0; mt < 4; mt++)
            ldsm4(af[0][mt], aTile + swoff(aRow + mt * 16, aChk) * 4u);
        #pragma unroll
        for (int j = 0; j < 2; j++)
            ldsm4(&bf[0][2 * j][0], bTile + swoff(bRow + j * 16, bChk) * 4u);

        #pragma unroll
        for (int kk = 0; kk < 2; kk++) {
            if (kk == 0) {
                #pragma unroll
                for (int mt = 0; mt < 4; mt++)
                    ldsm4(af[1][mt], aTile + swoff(aRow + mt * 16, aChk + 2) * 4u);
                #pragma unroll
                for (int j = 0; j < 2; j++)
                    ldsm4(&bf[1][2 * j][0], bTile + swoff(bRow + j * 16, bChk + 2) * 4u);
            }
            #pragma unroll
            for (int mt = 0; mt < 4; mt++)
                #pragma unroll
                for (int nt = 0; nt < 4; nt++)
                    mma16(acc[mt][nt], af[kk][mt], bf[kk][nt]);
        }
    }

    // ---- epilogue ----
    const int rA = lane >> 2, cA = lane & 3;

    if constexpr (EPI == 2) {
        __nv_bfloat16* Cb = (__nv_bfloat16*)Cv + sC * bz;
        float* rs = res + (size_t)bz * kHW;
        #pragma unroll
        for (int mt = 0; mt < 4; mt++) {
            const int r0 = m0 + wm * 64 + mt * 16 + rA;
            float s0 = 0.f, s1 = 0.f;
            #pragma unroll
            for (int nt = 0; nt < 4; nt++) {
                const int col = n0 + wn * 32 + nt * 8 + cA * 2;
                const float e0 = ex2(acc[mt][nt][0] * alpha);
                const float e1 = ex2(acc[mt][nt][1] * alpha);
                const float e2 = ex2(acc[mt][nt][2] * alpha);
                const float e3 = ex2(acc[mt][nt][3] * alpha);
                const __nv_bfloat162 w0 = __floats2bfloat162_rn(e0, e1);
                const __nv_bfloat162 w1 = __floats2bfloat162_rn(e2, e3);
                *(__nv_bfloat162*)(Cb + (size_t)r0 * ldc + col)       = w0;
                *(__nv_bfloat162*)(Cb + (size_t)(r0 + 8) * ldc + col) = w1;
                s0 += __low2float(w0) + __high2float(w0);
                s1 += __low2float(w1) + __high2float(w1);
            }
            s0 += __shfl_xor_sync(0xffffffffu, s0, 1);
            s0 += __shfl_xor_sync(0xffffffffu, s0, 2);
            s1 += __shfl_xor_sync(0xffffffffu, s1, 1);
            s1 += __shfl_xor_sync(0xffffffffu, s1, 2);
            if (cA == 0) {
                atomicAdd(&rs[r0], s0);
                atomicAdd(&rs[r0 + 8], s1);
            }
        }
        return;
    }

    #pragma unroll
    for (int mt = 0; mt < 4; mt++) {
        const int r0 = m0 + wm * 64 + mt * 16 + rA;
        float bm0 = 0.f, bm1 = 0.f;
        if (EPI == 4) { bm0 = bias[r0]; bm1 = bias[r0 + 8]; }
        if (EPI == 5) {
            bm0 = 1.f / bias[(size_t)bz * kHW + r0];
            bm1 = 1.f / bias[(size_t)bz * kHW + r0 + 8];
        }
        #pragma unroll
        for (int nt = 0; nt < 4; nt++) {
            const int col = n0 + wn * 32 + nt * 8 + cA * 2;
            float d0 = acc[mt][nt][0], d1 = acc[mt][nt][1];
            float d2 = acc[mt][nt][2], d3 = acc[mt][nt][3];
            if (EPI == 4) {
                d0 += bm0; d1 += bm0; d2 += bm1; d3 += bm1;
            } else if (EPI == 5) {
                d0 *= bm0; d1 *= bm0; d2 *= bm1; d3 *= bm1;
            }
            if (EPI == 4) {
                const float* rp = res + sC * bz;
                d0 += rp[(size_t)r0 * ldc + col];
                d1 += rp[(size_t)r0 * ldc + col + 1];
                d2 += rp[(size_t)(r0 + 8) * ldc + col];
                d3 += rp[(size_t)(r0 + 8) * ldc + col + 1];
                float* Cb = (float*)Cv + sC * bz;
                *(float2*)(Cb + (size_t)r0 * ldc + col)       = make_float2(d0, d1);
                *(float2*)(Cb + (size_t)(r0 + 8) * ldc + col) = make_float2(d2, d3);
            } else {
                __nv_bfloat16* Cb = (__nv_bfloat16*)Cv + sC * bz;
                *(__nv_bfloat162*)(Cb + (size_t)r0 * ldc + col) =
                    __floats2bfloat162_rn(d0, d1);
                *(__nv_bfloat162*)(Cb + (size_t)(r0 + 8) * ldc + col) =
                    __floats2bfloat162_rn(d2, d3);
            }
        }
    }
}

// ---------------------------------------------------------------------------
extern "C" void kernel_launch(void* const* d_in, const int* in_sizes, int n_in,
                              void* d_out, int out_size) {
    const float* x     = (const float*)d_in[0];
    const float* gamma = (const float*)d_in[1];
    const float* beta  = (const float*)d_in[2];
    const float* wq    = (const float*)d_in[3];
    const float* bq    = (const float*)d_in[4];
    const float* wk    = (const float*)d_in[5];
    const float* bk    = (const float*)d_in[6];
    const float* wv    = (const float*)d_in[7];
    const float* bv    = (const float*)d_in[8];
    const float* wo    = (const float*)d_in[9];
    const float* bo    = (const float*)d_in[10];
    float* out = (float*)d_out;

    __nv_bfloat16 *hT, *qkt, *v, *o2, *simh, *wh;
    float *aff, *rs, *bqk;
    cudaGetSymbolAddress((void**)&hT,   g_hT);
    cudaGetSymbolAddress((void**)&qkt,  g_qkt);
    cudaGetSymbolAddress((void**)&v,    g_v);
    cudaGetSymbolAddress((void**)&o2,   g_o2);
    cudaGetSymbolAddress((void**)&simh, g_simh);
    cudaGetSymbolAddress((void**)&aff,  g_aff);
    cudaGetSymbolAddress((void**)&rs,   g_rs);
    cudaGetSymbolAddress((void**)&wh,   g_wh);
    cudaGetSymbolAddress((void**)&bqk,  g_bqk);

    const size_t sNC = (size_t)kHW * kC;
    const size_t sQK = (size_t)kHW * 1024;
    const size_t sNN = (size_t)kHW * kHW;
    const float  scale2 = (1.0f / sqrtf((float)kC)) * 1.4426950408889634f;
    const int nW = kC * kC;

    // 0) prep: weights->bf16, bias concat, rs zero
    prep_all<<<256, 256>>>(wq, wk, wv, wo, bq, bk, wh, bqk, rs);

    // 1) GroupNorm
    gn_stats<<<kB * kG, 512>>>(x, gamma, beta, aff);
    gn_norm_t<<<dim3(kHW / 128, kC / 32, kB), dim3(32, 8)>>>(x, aff, hT);

    // 2) merged QK + V projections (one launch, 384 CTAs per batch)
    gemm_qkv<<<dim3(384, 1, kB), 256>>>(hT, wh, bqk, bv, qkt, v);

    // 3) P~ = exp2(scale2 * Qt@Kt^T) -> bf16, + row sums (M=N=4096, K=512)
    {
        dim3 grid(kHW / 128, kHW / 128, kB);
        gemm_bf16<2><<<grid, 256>>>(qkt, qkt + 512, nullptr, rs, simh,
                                    1024, 1024, kHW, kC, sQK, sQK, sNN, scale2);
    }
    // 4) o2 = (P~ @ V^T) / rowsum  (M=4096, N=512, K=4096), output [n][c] bf16
    {
        dim3 grid(kC / 128, kHW / 128, kB);
        gemm_bf16<5><<<grid, 256>>>(simh, v, rs, nullptr, o2,
                                    kHW, kHW, kC, kHW, sNN, sNC, sNC, 1.f);
    }
    // 5) out = x + Wo @ o2^T + bo  (M=512, N=4096, K=512), f32 out
    {
        dim3 grid(kHW / 128, kC / 128, kB);
        gemm_bf16<4><<<grid, 256>>>(wh + 3 * nW, o2, bo, (float*)x, out,
                                    kC, kC, kHW, kC, 0, sNC, sNC, 1.f);
    }
}

// round 17
// speedup vs baseline: 1.3680x; 1.0050x over previous
#include <cuda_runtime.h>
#include <cuda_bf16.h>
#include <cstdint>
#include <math.h>

// ---------------------------------------------------------------------------
// Problem constants
// ---------------------------------------------------------------------------
constexpr int kB  = 4;
constexpr int kC  = 512;
constexpr int kHW = 4096;
constexpr int kG  = 32;
constexpr int kCPG = kC / kG;   // 16
constexpr float kEPS = 1e-6f;

// Scratch (__device__ globals per allocation-free rule)
__device__ __nv_bfloat16 g_hT  [(size_t)kB * kHW * kC];    // GN out [b][n][c]
__device__ __nv_bfloat16 g_qkt [(size_t)kB * kHW * 1024];  // [b][n][q||k]
__device__ __nv_bfloat16 g_v   [(size_t)kB * kC * kHW];    // V [b][c][n]
__device__ __nv_bfloat16 g_o2  [(size_t)kB * kHW * kC];    // attn@V [b][n][c]
__device__ __nv_bfloat16 g_simh[(size_t)kB * kHW * kHW];   // P~ bf16 (128 MB)
__device__ float         g_rs  [(size_t)kB * kHW];         // softmax row sums
__device__ float         g_aff [(size_t)kB * kC * 2];      // (scale, offset)
__device__ __nv_bfloat16 g_wh  [4 * kC * kC];              // bf16 wq,wk,wv,wo
__device__ float         g_bqk [2 * kC];                   // bq || bk

// ---------------------------------------------------------------------------
// Helpers
// ---------------------------------------------------------------------------
__device__ __forceinline__ uint32_t smem_u32(const void* p) {
    uint32_t a;
    asm("{ .reg .u64 t; cvta.to.shared.u64 t, %1; cvt.u32.u64 %0, t; }"
        : "=r"(a) : "l"(p));
    return a;
}
__device__ __forceinline__ void cp16(uint32_t dst, const void* src) {
    asm volatile("cp.async.cg.shared.global [%0], [%1], 16;\n"
                 :: "r"(dst), "l"(src));
}
__device__ __forceinline__ void cp_commit() {
    asm volatile("cp.async.commit_group;\n" ::: "memory");
}
template <int N>
__device__ __forceinline__ void cp_wait() {
    asm volatile("cp.async.wait_group %0;\n" :: "n"(N) : "memory");
}
// single-instruction exp2 (MUFU.EX2)
__device__ __forceinline__ float ex2(float x) {
    float y;
    asm("ex2.approx.ftz.f32 %0, %1;" : "=f"(y) : "f"(x));
    return y;
}
// m16n8k16 bf16 mma, row.col, fp32 accum
__device__ __forceinline__ void mma16(float* d, const uint32_t* a, const uint32_t* b) {
    asm volatile(
        "mma.sync.aligned.m16n8k16.row.col.f32.bf16.bf16.f32 "
        "{%0,%1,%2,%3}, {%4,%5,%6,%7}, {%8,%9}, {%0,%1,%2,%3};"
        : "+f"(d[0]), "+f"(d[1]), "+f"(d[2]), "+f"(d[3])
        : "r"(a[0]), "r"(a[1]), "r"(a[2]), "r"(a[3]), "r"(b[0]), "r"(b[1]));
}
// ldmatrix 4x (m8n8 b16)
__device__ __forceinline__ void ldsm4(uint32_t* r, uint32_t addr) {
    asm volatile(
        "ldmatrix.sync.aligned.m8n8.x4.shared.b16 {%0,%1,%2,%3}, [%4];"
        : "=r"(r[0]), "=r"(r[1]), "=r"(r[2]), "=r"(r[3]) : "r"(addr));
}

// ---------------------------------------------------------------------------
// Prep: weights -> bf16 (float4), bias concat, rs zero. 256 blocks x 256 thr.
// ---------------------------------------------------------------------------
__global__ void prep_all(const float* __restrict__ wq, const float* __restrict__ wk,
                         const float* __restrict__ wv, const float* __restrict__ wo,
                         const float* __restrict__ bq, const float* __restrict__ bk,
                         __nv_bfloat16* __restrict__ wh, float* __restrict__ bqk,
                         float* __restrict__ rs) {
    const int i = blockIdx.x * blockDim.x + threadIdx.x;   // 0..65535
    const int n4 = kC * kC / 4;                            // 65536
    __nv_bfloat162* wh2 = (__nv_bfloat162*)wh;
    if (i < n4) {
        const float4 a = ((const float4*)wq)[i];
        const float4 b = ((const float4*)wk)[i];
        const float4 c = ((const float4*)wv)[i];
        const float4 d = ((const float4*)wo)[i];
        wh2[0 * n4 * 2 + 2 * i + 0] = __floats2bfloat162_rn(a.x, a.y);
        wh2[0 * n4 * 2 + 2 * i + 1] = __floats2bfloat162_rn(a.z, a.w);
        wh2[1 * n4 * 2 + 2 * i + 0] = __floats2bfloat162_rn(b.x, b.y);
        wh2[1 * n4 * 2 + 2 * i + 1] = __floats2bfloat162_rn(b.z, b.w);
        wh2[2 * n4 * 2 + 2 * i + 0] = __floats2bfloat162_rn(c.x, c.y);
        wh2[2 * n4 * 2 + 2 * i + 1] = __floats2bfloat162_rn(c.z, c.w);
        wh2[3 * n4 * 2 + 2 * i + 0] = __floats2bfloat162_rn(d.x, d.y);
        wh2[3 * n4 * 2 + 2 * i + 1] = __floats2bfloat162_rn(d.z, d.w);
    }
    if (i < kC)               bqk[i] = bq[i];
    else if (i < 2 * kC)      bqk[i] = bk[i - kC];
    if (i < kB * kHW)         rs[i] = 0.f;
}

// ---------------------------------------------------------------------------
// GroupNorm pass 1: per-(b,g) mean/var -> per-channel affine (float4, 512 thr)
// ---------------------------------------------------------------------------
__global__ void gn_stats(const float* __restrict__ x,
                         const float* __restrict__ gamma,
                         const float* __restrict__ beta,
                         float* __restrict__ aff) {
    const int b = blockIdx.x / kG, g = blockIdx.x % kG;
    const float4* xp = (const float4*)(x + ((size_t)b * kC + (size_t)g * kCPG) * kHW);
    const int N4 = kCPG * kHW / 4;    // 16384

    float s = 0.f, ss = 0.f;
    for (int i = threadIdx.x; i < N4; i += 512) {
        const float4 v = xp[i];
        s  += v.x + v.y + v.z + v.w;
        ss += v.x * v.x + v.y * v.y + v.z * v.z + v.w * v.w;
    }
    __shared__ float sh1[512], sh2[512];
    sh1[threadIdx.x] = s; sh2[threadIdx.x] = ss;
    __syncthreads();
    for (int o = 256; o > 0; o >>= 1) {
        if (threadIdx.x < o) {
            sh1[threadIdx.x] += sh1[threadIdx.x + o];
            sh2[threadIdx.x] += sh2[threadIdx.x + o];
        }
        __syncthreads();
    }
    if (threadIdx.x < kCPG) {
        const float N = (float)(kCPG * kHW);
        const float mean = sh1[0] / N;
        const float var  = sh2[0] / N - mean * mean;
        const float rinv = rsqrtf(var + kEPS);
        const int ch = g * kCPG + threadIdx.x;
        const float a = rinv * gamma[ch];
        aff[((size_t)b * kC + ch) * 2 + 0] = a;
        aff[((size_t)b * kC + ch) * 2 + 1] = beta[ch] - mean * a;
    }
}

// ---------------------------------------------------------------------------
// GroupNorm pass 2: normalize + transpose + bf16: x[b][c][n] -> hT[b][n][c]
// Tile 128n x 32c, block (32,8). float4 loads, bf16x2 stores.
// ---------------------------------------------------------------------------
__global__ void gn_norm_t(const float* __restrict__ x,
                          const float* __restrict__ aff,
                          __nv_bfloat16* __restrict__ hT) {
    __shared__ float t[32][129];
    const int b = blockIdx.z;
    const int n0 = blockIdx.x * 128, c0 = blockIdx.y * 32;
    const int tx = threadIdx.x, ty = threadIdx.y;   // 32 x 8
    const int tid = ty * 32 + tx;
    const float* xb = x  + (size_t)b * kC * kHW;
    __nv_bfloat16* hb = hT + (size_t)b * kHW * kC;

    #pragma unroll
    for (int r = 0; r < 4; r++) {
        const int cl = ty + r * 8;                   // 0..31
        const int c = c0 + cl;
        const float a  = aff[((size_t)b * kC + c) * 2 + 0];
        const float bb = aff[((size_t)b * kC + c) * 2 + 1];
        const float4 v = *(const float4*)(xb + (size_t)c * kHW + n0 + tx * 4);
        t[cl][tx * 4 + 0] = v.x * a + bb;
        t[cl][tx * 4 + 1] = v.y * a + bb;
        t[cl][tx * 4 + 2] = v.z * a + bb;
        t[cl][tx * 4 + 3] = v.w * a + bb;
    }
    __syncthreads();
    const int c2 = (tid & 15) * 2;
    #pragma unroll
    for (int rr = 0; rr < 8; rr++) {
        const int nl = (tid >> 4) + rr * 16;         // 0..127
        *(__nv_bfloat162*)(hb + (size_t)(n0 + nl) * kC + c0 + c2) =
            __floats2bfloat162_rn(t[c2][nl], t[c2 + 1][nl]);
    }
}

// ---------------------------------------------------------------------------
// Shared GEMM constants (128x128x32 tile, 3-stage, lead 2, 2 CTAs/SM)
// ---------------------------------------------------------------------------
constexpr int kRowW   = 16;              // words per tile row (32 bf16)
constexpr int kTileW  = 128 * kRowW;     // 2048 words = 8 KB per tile
constexpr int kStageW = 2 * kTileW;      // A + B = 16 KB per stage
constexpr int kNS     = 3;               // stages (48 KB total)

__device__ __forceinline__ uint32_t swoff(int row, int c) {
    return (uint32_t)(row * kRowW + ((c ^ ((row >> 1) & 3)) << 2));
}

// ---------------------------------------------------------------------------
// Merged QK + V projection GEMM (both consume hT, K=512).
// grid (384, 1, kB): id<256 -> QK tile (nx=id%8, my=id/8), N=1024, col bias.
//                    id>=256 -> V tile (nx=(id-256)%32, my=(id-256)/32), row bias.
// Stage rotation is modulo-free (cur/nxt/pre registers), unroll 3.
// ---------------------------------------------------------------------------
__global__ void __launch_bounds__(256, 2)
gemm_qkv(const __nv_bfloat16* __restrict__ hT, const __nv_bfloat16* __restrict__ wh,
         const float* __restrict__ bqk, const float* __restrict__ bv,
         __nv_bfloat16* __restrict__ qkt, __nv_bfloat16* __restrict__ vout) {
    __shared__ __align__(16) uint32_t sm[kNS * kStageW];
    const int tid = threadIdx.x;
    const int lane = tid & 31, wid = tid >> 5;
    const int wm = wid & 1, wn = wid >> 1;

    const int bz = blockIdx.z;
    const int id = blockIdx.x;
    const bool isV = (id >= 256);
    const int nx = isV ? (id - 256) % 32 : id % 8;
    const int my = isV ? (id - 256) / 32 : id / 8;
    const int m0 = my * 128;
    const int n0 = nx * 128;

    const __nv_bfloat16* hb = hT + (size_t)bz * kHW * kC;
    const __nv_bfloat16* A = isV ? wh + 2 * kC * kC : hb;   // lda = 512
    const __nv_bfloat16* B = isV ? hb : wh;                  // ldb = 512

    const uint32_t smAddr = smem_u32(sm);
    constexpr int KT = kC / 32;    // 16

    const int lg   = lane >> 3;
    const int lrow = lane & 7;
    const int aRow = wm * 64 + (lg & 1) * 8 + lrow;
    const int aChk = lg >> 1;
    const int bRow = wn * 32 + (lg >> 1) * 8 + lrow;
    const int bChk = lg & 1;

    const int pr0 = tid >> 2, pc0 = tid & 3;
    const int pr1 = (256 + tid) >> 2, pc1 = (256 + tid) & 3;
    const uint32_t pOff0 = swoff(pr0, pc0) * 4u;
    const uint32_t pOff1 = swoff(pr1, pc1) * 4u;
    const __nv_bfloat16* gA0 = A + (size_t)(m0 + pr0) * kC + pc0 * 8;
    const __nv_bfloat16* gA1 = A + (size_t)(m0 + pr1) * kC + pc1 * 8;
    const __nv_bfloat16* gB0 = B + (size_t)(n0 + pr0) * kC + pc0 * 8;
    const __nv_bfloat16* gB1 = B + (size_t)(n0 + pr1) * kC + pc1 * 8;

    // prefetch directly to a stage base address (no modulo)
    auto prefetch = [&](int it, uint32_t stage) {
        const int k0 = it * 32;
        const uint32_t bBase = stage + (uint32_t)kTileW * 4u;
        cp16(stage + pOff0, gA0 + k0);
        cp16(stage + pOff1, gA1 + k0);
        cp16(bBase + pOff0, gB0 + k0);
        cp16(bBase + pOff1, gB1 + k0);
    };

    float acc[4][4][4];
    #pragma unroll
    for (int i = 0; i < 4; i++)
        #pragma unroll
        for (int j = 0; j < 4; j++)
            #pragma unroll
            for (int r = 0; r < 4; r++) acc[i][j][r] = 0.f;

    uint32_t cur = smAddr;
    uint32_t nxt = smAddr + (uint32_t)kStageW * 4u;
    uint32_t pre = smAddr + (uint32_t)(2 * kStageW) * 4u;

    prefetch(0, cur); cp_commit();
    prefetch(1, nxt); cp_commit();

    uint32_t af[2][4][4];
    uint32_t bf[2][4][2];

    #pragma unroll 3
    for (int it = 0; it < KT; ++it) {
        cp_wait<1>();
        __syncthreads();
        if (it + 2 < KT) prefetch(it + 2, pre);
        cp_commit();

        const uint32_t aTile = cur;
        const uint32_t bTile = cur + (uint32_t)kTileW * 4u;

        #pragma unroll
        for (int mt = 0; mt < 4; mt++)
            ldsm4(af[0][mt], aTile + swoff(aRow + mt * 16, aChk) * 4u);
        #pragma unroll
        for (int j = 0; j < 2; j++)
            ldsm4(&bf[0][2 * j][0], bTile + swoff(bRow + j * 16, bChk) * 4u);

        #pragma unroll
        for (int kk = 0; kk < 2; kk++) {
            if (kk == 0) {
                #pragma unroll
                for (int mt = 0; mt < 4; mt++)
                    ldsm4(af[1][mt], aTile + swoff(aRow + mt * 16, aChk + 2) * 4u);
                #pragma unroll
                for (int j = 0; j < 2; j++)
                    ldsm4(&bf[1][2 * j][0], bTile + swoff(bRow + j * 16, bChk + 2) * 4u);
            }
            #pragma unroll
            for (int mt = 0; mt < 4; mt++)
                #pragma unroll
                for (int nt = 0; nt < 4; nt++)
                    mma16(acc[mt][nt], af[kk][mt], bf[kk][nt]);
        }
        const uint32_t t = cur; cur = nxt; nxt = pre; pre = t;
    }

    // epilogue
    const int rA = lane >> 2, cA = lane & 3;
    const int ldc = isV ? kHW : 1024;
    __nv_bfloat16* Cb = isV ? vout + (size_t)bz * kC * kHW
                            : qkt + (size_t)bz * kHW * 1024;
    #pragma unroll
    for (int mt = 0; mt < 4; mt++) {
        const int r0 = m0 + wm * 64 + mt * 16 + rA;
        float bm0 = 0.f, bm1 = 0.f;
        if (isV) { bm0 = bv[r0]; bm1 = bv[r0 + 8]; }
        #pragma unroll
        for (int nt = 0; nt < 4; nt++) {
            const int col = n0 + wn * 32 + nt * 8 + cA * 2;
            float d0 = acc[mt][nt][0], d1 = acc[mt][nt][1];
            float d2 = acc[mt][nt][2], d3 = acc[mt][nt][3];
            if (isV) {
                d0 += bm0; d1 += bm0; d2 += bm1; d3 += bm1;
            } else {
                const float b0 = bqk[col], b1 = bqk[col + 1];
                d0 += b0; d1 += b1; d2 += b0; d3 += b1;
            }
            *(__nv_bfloat162*)(Cb + (size_t)r0 * ldc + col) =
                __floats2bfloat162_rn(d0, d1);
            *(__nv_bfloat162*)(Cb + (size_t)(r0 + 8) * ldc + col) =
                __floats2bfloat162_rn(d2, d3);
        }
    }
}

// ---------------------------------------------------------------------------
// General GEMM (verified mainloop, modulo-free stage rotation, unroll 3).
// EPI: 2=ex2(alpha*acc)->bf16 + atomic row-sum (softmax numerator),
//      4=+bias[m]+res[m][n]->f32, 5=acc/rowsum[m]->bf16
// ---------------------------------------------------------------------------
template <int EPI>
__global__ void __launch_bounds__(256, 2)
gemm_bf16(const __nv_bfloat16* __restrict__ A, const __nv_bfloat16* __restrict__ B,
          const float* __restrict__ bias, float* __restrict__ res,
          void* __restrict__ Cv,
          int lda, int ldb, int ldc, int K,
          size_t sA, size_t sB, size_t sC, float alpha) {
    __shared__ __align__(16) uint32_t sm[kNS * kStageW];
    const int tid = threadIdx.x;
    const int lane = tid & 31, wid = tid >> 5;
    const int wm = wid & 1, wn = wid >> 1;

    const int bz = blockIdx.z;
    const int m0 = blockIdx.y * 128;
    const int n0 = blockIdx.x * 128;

    const uint32_t smAddr = smem_u32(sm);
    const int KT = K / 32;

    const int lg   = lane >> 3;
    const int lrow = lane & 7;
    const int aRow = wm * 64 + (lg & 1) * 8 + lrow;
    const int aChk = lg >> 1;
    const int bRow = wn * 32 + (lg >> 1) * 8 + lrow;
    const int bChk = lg & 1;

    const int pr0 = tid >> 2, pc0 = tid & 3;
    const int pr1 = (256 + tid) >> 2, pc1 = (256 + tid) & 3;
    const uint32_t pOff0 = swoff(pr0, pc0) * 4u;
    const uint32_t pOff1 = swoff(pr1, pc1) * 4u;
    const __nv_bfloat16* gA0 = A + sA * bz + (size_t)(m0 + pr0) * lda + pc0 * 8;
    const __nv_bfloat16* gA1 = A + sA * bz + (size_t)(m0 + pr1) * lda + pc1 * 8;
    const __nv_bfloat16* gB0 = B + sB * bz + (size_t)(n0 + pr0) * ldb + pc0 * 8;
    const __nv_bfloat16* gB1 = B + sB * bz + (size_t)(n0 + pr1) * ldb + pc1 * 8;

    auto prefetch = [&](int it, uint32_t stage) {
        const int k0 = it * 32;
        const uint32_t bBase = stage + (uint32_t)kTileW * 4u;
        cp16(stage + pOff0, gA0 + k0);
        cp16(stage + pOff1, gA1 + k0);
        cp16(bBase + pOff0, gB0 + k0);
        cp16(bBase + pOff1, gB1 + k0);
    };

    float acc[4][4][4];
    #pragma unroll
    for (int i = 0; i < 4; i++)
        #pragma unroll
        for (int j = 0; j < 4; j++)
            #pragma unroll
            for (int r = 0; r < 4; r++) acc[i][j][r] = 0.f;

    uint32_t cur = smAddr;
    uint32_t nxt = smAddr + (uint32_t)kStageW * 4u;
    uint32_t pre = smAddr + (uint32_t)(2 * kStageW) * 4u;

    prefetch(0, cur); cp_commit();
    prefetch(1, nxt); cp_commit();

    uint32_t af[2][4][4];
    uint32_t bf[2][4][2];

    #pragma unroll 3
    for (int it = 0; it < KT; ++it) {
        cp_wait<1>();
        __syncthreads();
        if (it + 2 < KT) prefetch(it + 2, pre);
        cp_commit();

        const uint32_t aTile = cur;
        const uint32_t bTile = cur + (uint32_t)kTileW * 4u;

        #pragma unroll
        for (int mt = 0; mt < 4; mt++)
            ldsm4(af[0][mt], aTile + swoff(aRow + mt * 16, aChk) * 4u);
        #pragma unroll
        for (int j = 0; j < 2; j++)
            ldsm4(&bf[0][2 * j][0], bTile + swoff(bRow + j * 16, bChk) * 4u);

        #pragma unroll
        for (int kk = 0; kk < 2; kk++) {
            if (kk == 0) {
                #pragma unroll
                for (int mt = 0; mt < 4; mt++)
                    ldsm4(af[1][mt], aTile + swoff(aRow + mt * 16, aChk + 2) * 4u);
                #pragma unroll
                for (int j = 0; j < 2; j++)
                    ldsm4(&bf[1][2 * j][0], bTile + swoff(bRow + j * 16, bChk + 2) * 4u);
            }
            #pragma unroll
            for (int mt = 0; mt < 4; mt++)
                #pragma unroll
                for (int nt = 0; nt < 4; nt++)
                    mma16(acc[mt][nt], af[kk][mt], bf[kk][nt]);
        }
        const uint32_t t = cur; cur = nxt; nxt = pre; pre = t;
    }

    // ---- epilogue ----
    const int rA = lane >> 2, cA = lane & 3;

    if constexpr (EPI == 2) {
        __nv_bfloat16* Cb = (__nv_bfloat16*)Cv + sC * bz;
        float* rs = res + (size_t)bz * kHW;
        #pragma unroll
        for (int mt = 0; mt < 4; mt++) {
            const int r0 = m0 + wm * 64 + mt * 16 + rA;
            float s0 = 0.f, s1 = 0.f;
            #pragma unroll
            for (int nt = 0; nt < 4; nt++) {
                const int col = n0 + wn * 32 + nt * 8 + cA * 2;
                const float e0 = ex2(acc[mt][nt][0] * alpha);
                const float e1 = ex2(acc[mt][nt][1] * alpha);
                const float e2 = ex2(acc[mt][nt][2] * alpha);
                const float e3 = ex2(acc[mt][nt][3] * alpha);
                const __nv_bfloat162 w0 = __floats2bfloat162_rn(e0, e1);
                const __nv_bfloat162 w1 = __floats2bfloat162_rn(e2, e3);
                *(__nv_bfloat162*)(Cb + (size_t)r0 * ldc + col)       = w0;
                *(__nv_bfloat162*)(Cb + (size_t)(r0 + 8) * ldc + col) = w1;
                s0 += __low2float(w0) + __high2float(w0);
                s1 += __low2float(w1) + __high2float(w1);
            }
            s0 += __shfl_xor_sync(0xffffffffu, s0, 1);
            s0 += __shfl_xor_sync(0xffffffffu, s0, 2);
            s1 += __shfl_xor_sync(0xffffffffu, s1, 1);
            s1 += __shfl_xor_sync(0xffffffffu, s1, 2);
            if (cA == 0) {
                atomicAdd(&rs[r0], s0);
                atomicAdd(&rs[r0 + 8], s1);
            }
        }
        return;
    }

    #pragma unroll
    for (int mt = 0; mt < 4; mt++) {
        const int r0 = m0 + wm * 64 + mt * 16 + rA;
        float bm0 = 0.f, bm1 = 0.f;
        if (EPI == 4) { bm0 = bias[r0]; bm1 = bias[r0 + 8]; }
        if (EPI == 5) {
            bm0 = 1.f / bias[(size_t)bz * kHW + r0];
            bm1 = 1.f / bias[(size_t)bz * kHW + r0 + 8];
        }
        #pragma unroll
        for (int nt = 0; nt < 4; nt++) {
            const int col = n0 + wn * 32 + nt * 8 + cA * 2;
            float d0 = acc[mt][nt][0], d1 = acc[mt][nt][1];
            float d2 = acc[mt][nt][2], d3 = acc[mt][nt][3];
            if (EPI == 4) {
                d0 += bm0; d1 += bm0; d2 += bm1; d3 += bm1;
            } else if (EPI == 5) {
                d0 *= bm0; d1 *= bm0; d2 *= bm1; d3 *= bm1;
            }
            if (EPI == 4) {
                const float* rp = res + sC * bz;
                d0 += rp[(size_t)r0 * ldc + col];
                d1 += rp[(size_t)r0 * ldc + col + 1];
                d2 += rp[(size_t)(r0 + 8) * ldc + col];
                d3 += rp[(size_t)(r0 + 8) * ldc + col + 1];
                float* Cb = (float*)Cv + sC * bz;
                *(float2*)(Cb + (size_t)r0 * ldc + col)       = make_float2(d0, d1);
                *(float2*)(Cb + (size_t)(r0 + 8) * ldc + col) = make_float2(d2, d3);
            } else {
                __nv_bfloat16* Cb = (__nv_bfloat16*)Cv + sC * bz;
                *(__nv_bfloat162*)(Cb + (size_t)r0 * ldc + col) =
                    __floats2bfloat162_rn(d0, d1);
                *(__nv_bfloat162*)(Cb + (size_t)(r0 + 8) * ldc + col) =
                    __floats2bfloat162_rn(d2, d3);
            }
        }
    }
}

// ---------------------------------------------------------------------------
extern "C" void kernel_launch(void* const* d_in, const int* in_sizes, int n_in,
                              void* d_out, int out_size) {
    const float* x     = (const float*)d_in[0];
    const float* gamma = (const float*)d_in[1];
    const float* beta  = (const float*)d_in[2];
    const float* wq    = (const float*)d_in[3];
    const float* bq    = (const float*)d_in[4];
    const float* wk    = (const float*)d_in[5];
    const float* bk    = (const float*)d_in[6];
    const float* wv    = (const float*)d_in[7];
    const float* bv    = (const float*)d_in[8];
    const float* wo    = (const float*)d_in[9];
    const float* bo    = (const float*)d_in[10];
    float* out = (float*)d_out;

    __nv_bfloat16 *hT, *qkt, *v, *o2, *simh, *wh;
    float *aff, *rs, *bqk;
    cudaGetSymbolAddress((void**)&hT,   g_hT);
    cudaGetSymbolAddress((void**)&qkt,  g_qkt);
    cudaGetSymbolAddress((void**)&v,    g_v);
    cudaGetSymbolAddress((void**)&o2,   g_o2);
    cudaGetSymbolAddress((void**)&simh, g_simh);
    cudaGetSymbolAddress((void**)&aff,  g_aff);
    cudaGetSymbolAddress((void**)&rs,   g_rs);
    cudaGetSymbolAddress((void**)&wh,   g_wh);
    cudaGetSymbolAddress((void**)&bqk,  g_bqk);

    const size_t sNC = (size_t)kHW * kC;
    const size_t sQK = (size_t)kHW * 1024;
    const size_t sNN = (size_t)kHW * kHW;
    const float  scale2 = (1.0f / sqrtf((float)kC)) * 1.4426950408889634f;
    const int nW = kC * kC;

    // 0) prep: weights->bf16, bias concat, rs zero
    prep_all<<<256, 256>>>(wq, wk, wv, wo, bq, bk, wh, bqk, rs);

    // 1) GroupNorm
    gn_stats<<<kB * kG, 512>>>(x, gamma, beta, aff);
    gn_norm_t<<<dim3(kHW / 128, kC / 32, kB), dim3(32, 8)>>>(x, aff, hT);

    // 2) merged QK + V projections (one launch, 384 CTAs per batch)
    gemm_qkv<<<dim3(384, 1, kB), 256>>>(hT, wh, bqk, bv, qkt, v);

    // 3) P~ = exp2(scale2 * Qt@Kt^T) -> bf16, + row sums (M=N=4096, K=512)
    {
        dim3 grid(kHW / 128, kHW / 128, kB);
        gemm_bf16<2><<<grid, 256>>>(qkt, qkt + 512, nullptr, rs, simh,
                                    1024, 1024, kHW, kC, sQK, sQK, sNN, scale2);
    }
    // 4) o2 = (P~ @ V^T) / rowsum  (M=4096, N=512, K=4096), output [n][c] bf16
    {
        dim3 grid(kC / 128, kHW / 128, kB);
        gemm_bf16<5><<<grid, 256>>>(simh, v, rs, nullptr, o2,
                                    kHW, kHW, kC, kHW, sNN, sNC, sNC, 1.f);
    }
    // 5) out = x + Wo @ o2^T + bo  (M=512, N=4096, K=512), f32 out
    {
        dim3 grid(kHW / 128, kC / 128, kB);
        gemm_bf16<4><<<grid, 256>>>(wh + 3 * nW, o2, bo, (float*)x, out,
                                    kC, kC, kHW, kC, 0, sNC, sNC, 1.f);
    }
}